// round 12
// baseline (speedup 1.0000x reference)
#include <cuda_runtime.h>
#include <cuda_bf16.h>
#include <cstddef>
#include <cstdint>

// Problem constants
#define BB     128
#define TT     512
#define HALF_T 256
#define DD     512
#define NCLS   7
#define MROWS  (BB * HALF_T)   // 32768 rows fed to FFN / head

typedef unsigned long long ull;

// ---------------------------------------------------------------------------
// mma.sync / ldmatrix / cp.async / bulk-DMA helpers (baseline PTX, sm_100-safe)
// ---------------------------------------------------------------------------
__device__ __forceinline__ uint32_t smem_u32(const void* p) {
    uint32_t a;
    asm("{ .reg .u64 t; cvta.to.shared.u64 t, %1; cvt.u32.u64 %0, t; }"
        : "=r"(a) : "l"(p));
    return a;
}
__device__ __forceinline__ void ldsm4(uint32_t* r, uint32_t addr) {
    asm volatile("ldmatrix.sync.aligned.m8n8.x4.shared.b16 {%0,%1,%2,%3}, [%4];"
        : "=r"(r[0]), "=r"(r[1]), "=r"(r[2]), "=r"(r[3]) : "r"(addr));
}
__device__ __forceinline__ void mma_bf16(float* d, const uint32_t* a,
                                         uint32_t b0, uint32_t b1) {
    asm volatile("mma.sync.aligned.m16n8k16.row.col.f32.bf16.bf16.f32 "
        "{%0,%1,%2,%3}, {%4,%5,%6,%7}, {%8,%9}, {%0,%1,%2,%3};"
        : "+f"(d[0]), "+f"(d[1]), "+f"(d[2]), "+f"(d[3])
        : "r"(a[0]), "r"(a[1]), "r"(a[2]), "r"(a[3]), "r"(b0), "r"(b1));
}
__device__ __forceinline__ void cpasync16(uint32_t dst, const void* src) {
    asm volatile("cp.async.cg.shared.global [%0], [%1], 16;"
                 :: "r"(dst), "l"(src));
}
#define CP_COMMIT() asm volatile("cp.async.commit_group;" ::: "memory")

// bulk DMA: gmem -> smem, completion via mbarrier complete_tx
__device__ __forceinline__ void bulkcp(uint32_t dst, const void* src,
                                       uint32_t bytes, uint32_t mbar) {
    asm volatile(
        "cp.async.bulk.shared::cluster.global.mbarrier::complete_tx::bytes "
        "[%0], [%1], %2, [%3];"
        :: "r"(dst), "l"(src), "r"(bytes), "r"(mbar) : "memory");
}
__device__ __forceinline__ void mbar_init(uint32_t mbar, uint32_t cnt) {
    asm volatile("mbarrier.init.shared.b64 [%0], %1;"
                 :: "r"(mbar), "r"(cnt) : "memory");
}
__device__ __forceinline__ void mbar_expect(uint32_t mbar, uint32_t bytes) {
    asm volatile("mbarrier.arrive.expect_tx.shared.b64 _, [%0], %1;"
                 :: "r"(mbar), "r"(bytes) : "memory");
}
__device__ __forceinline__ void mbar_wait(uint32_t mbar, uint32_t parity) {
    asm volatile("{\n\t.reg .pred P;\n\tWL%=:\n\t"
                 "mbarrier.try_wait.parity.acquire.cta.shared::cta.b64 P, [%0], %1;\n\t"
                 "@!P bra WL%=;\n\t}" :: "r"(mbar), "r"(parity) : "memory");
}

// ---------------------------------------------------------------------------
// Device scratch
// ---------------------------------------------------------------------------
__device__ float g_gx[MROWS * 1536];             // input projections (fp32)
__device__ float g_x3[MROWS * DD];               // FFN layer-3 output (fp32)
__device__ __nv_bfloat16 g_A0 [MROWS * 1024];    // x0 split planes (hi|lo)
__device__ __nv_bfloat16 g_e2 [MROWS * 1024];    // emotions split planes
__device__ __nv_bfloat16 g_x1b[MROWS * 1024];
__device__ __nv_bfloat16 g_x2b[MROWS * 1024];
__device__ __nv_bfloat16 g_Wih2[1536 * 1024];    // weight split planes
__device__ __nv_bfloat16 g_W12 [512 * 1024];
__device__ __nv_bfloat16 g_W22 [512 * 1024];
__device__ __nv_bfloat16 g_W32 [512 * 1024];
// GRU h planes, padded layout for bulk DMA:
// [2 bufs][4 groups][2 planes][32 batches][520]  (row = plane*32+batch)
#define HROW 520
#define HGRP (2 * 32 * HROW)                     // 33280 elems / 66560 B
__device__ __nv_bfloat16 g_h2[2 * 4 * HGRP];
__device__ float g_Wc[NCLS * DD];
__device__ float g_s [NCLS];
__device__ float g_bc[NCLS];
__device__ unsigned g_ctr4[4 * 32];              // barrier counters, 128B apart

// ---------------------------------------------------------------------------
// Init: zero h planes buffer 0 + barrier counters (reset every graph replay)
// ---------------------------------------------------------------------------
__global__ void k_init() {
    int idx = blockIdx.x * 256 + threadIdx.x;   // 520 blocks = 133120 threads
    if (idx < 4 * HGRP / 2) {
        ((__nv_bfloat162*)g_h2)[idx] = __nv_bfloat162{__nv_bfloat16(0.f),
                                                      __nv_bfloat16(0.f)};
    }
    if (idx < 4) g_ctr4[idx * 32] = 0u;
}

// ---------------------------------------------------------------------------
// prep1/prep2: fold log_softmax + classifier head
// ---------------------------------------------------------------------------
__global__ void k_prep1(const float* __restrict__ W_half,
                        const float* __restrict__ W_out) {
    int idx = blockIdx.x * 256 + threadIdx.x;
    if (idx >= NCLS * DD) return;
    int n = idx / DD, k = idx % DD;
    float s = 0.0f;
    for (int j = 0; j < 256; j++)
        s += W_out[n * 256 + j] * W_half[j * DD + k];
    g_Wc[idx] = s;
}
__global__ void k_prep2(const float* __restrict__ W_out,
                        const float* __restrict__ b_half,
                        const float* __restrict__ b_out) {
    int tid = threadIdx.x;
    int w = tid >> 5, l = tid & 31;
    if (w < NCLS) {
        float s = 0.0f;
        #pragma unroll
        for (int i = 0; i < 16; i++) s += g_Wc[w * DD + i * 32 + l];
        #pragma unroll
        for (int off = 16; off > 0; off >>= 1)
            s += __shfl_xor_sync(0xffffffffu, s, off);
        if (l == 0) g_s[w] = s;
    }
    if (tid < NCLS) {
        float b = b_out[tid];
        for (int j = 0; j < 256; j++)
            b += W_out[tid * 256 + j] * b_half[j];
        g_bc[tid] = b;
    }
}

// ---------------------------------------------------------------------------
// k_split: fp32 [rows,512] -> bf16 hi/lo planes [rows,1024]
// ---------------------------------------------------------------------------
__global__ void k_split(const float* __restrict__ src,
                        __nv_bfloat16* __restrict__ dst,
                        int nrows, int perm) {
    int idx = blockIdx.x * 256 + threadIdx.x;
    if (idx >= nrows * 128) return;
    int r = idx >> 7, c4 = (idx & 127) << 2;
    size_t so = perm ? ((size_t)((r >> 8) * 512 + (r & 255)) * 512)
                     : ((size_t)r * 512);
    float4 v = *(const float4*)(src + so + c4);
    __nv_bfloat16 h[4], lo[4];
    float vv[4] = {v.x, v.y, v.z, v.w};
    #pragma unroll
    for (int i = 0; i < 4; i++) {
        h[i] = __float2bfloat16(vv[i]);
        lo[i] = __float2bfloat16(vv[i] - __bfloat162float(h[i]));
    }
    *(ull*)(dst + (size_t)r * 1024 + c4)       = *(ull*)h;
    *(ull*)(dst + (size_t)r * 1024 + 512 + c4) = *(ull*)lo;
}

// ---------------------------------------------------------------------------
// mma.sync bf16-split GEMM, 128x128 tile, 3-stage cp.async pipeline
// (exact R10 config — proven 549 us on gx).
// ---------------------------------------------------------------------------
#define ROWB 80          // padded smem row: 32 bf16 (64B) + 16B pad
#define BUFB (128 * ROWB)
#define NST  3
#define GEMM_SMEM (2 * NST * BUFB)   // 61440

__global__ void __launch_bounds__(256, 2)
k_mma_gemm(const __nv_bfloat16* __restrict__ A,
           const __nv_bfloat16* __restrict__ Bw,
           const float* __restrict__ bias,
           void* __restrict__ Cout,
           int Ntot, int n_tiles, int mode) {
    extern __shared__ __align__(16) char smc[];
    uint32_t sbase = smem_u32(smc);
    int tid = threadIdx.x, wid = tid >> 5, lane = tid & 31;
    int m0 = (blockIdx.x / n_tiles) << 7;
    int n0 = (blockIdx.x % n_tiles) << 7;

    int sr = tid >> 2;
    int sc = tid & 3;

    float acc[2][8][4];
    #pragma unroll
    for (int i = 0; i < 2; i++)
        #pragma unroll
        for (int j = 0; j < 8; j++)
            #pragma unroll
            for (int q = 0; q < 4; q++) acc[i][j][q] = 0.0f;

    auto issue = [&](int c) {
        int seg = c >> 4, kofs = (c & 15) << 5;
        int asel = (seg == 1) ? 512 : 0;
        int bsel = (seg == 2) ? 512 : 0;
        const __nv_bfloat16* Ag = A + (size_t)m0 * 1024 + asel + kofs;
        const __nv_bfloat16* Bg = Bw + (size_t)n0 * 1024 + bsel + kofs;
        int buf = c % NST;
        uint32_t da = sbase + (uint32_t)buf * BUFB;
        uint32_t db = sbase + (uint32_t)(NST + buf) * BUFB;
        cpasync16(da + sr * ROWB + sc * 16,        Ag + (size_t)sr * 1024 + sc * 8);
        cpasync16(da + (sr + 64) * ROWB + sc * 16, Ag + (size_t)(sr + 64) * 1024 + sc * 8);
        cpasync16(db + sr * ROWB + sc * 16,        Bg + (size_t)sr * 1024 + sc * 8);
        cpasync16(db + (sr + 64) * ROWB + sc * 16, Bg + (size_t)(sr + 64) * 1024 + sc * 8);
        CP_COMMIT();
    };

    issue(0);
    issue(1);

    int wm = wid & 3;
    int wn = wid >> 2;
    uint32_t a_row  = (uint32_t)(wm * 32 + (lane & 15));
    uint32_t a_colb = (uint32_t)((lane >> 4) * 16);
    uint32_t b_row  = (uint32_t)(wn * 64 + (lane & 7));
    uint32_t b_colb = (uint32_t)((lane >> 3) * 16);

    for (int c = 0; c < 48; c++) {
        if (c < 47) asm volatile("cp.async.wait_group 1;" ::: "memory");
        else        asm volatile("cp.async.wait_group 0;" ::: "memory");
        __syncthreads();
        if (c + 2 < 48) issue(c + 2);

        int buf = c % NST;
        uint32_t sA = sbase + (uint32_t)buf * BUFB;
        uint32_t sB = sbase + (uint32_t)(NST + buf) * BUFB;

        uint32_t bf[8][4];
        #pragma unroll
        for (int nt = 0; nt < 8; nt++)
            ldsm4(bf[nt], sB + (b_row + nt * 8) * ROWB + b_colb);

        #pragma unroll
        for (int ks = 0; ks < 2; ks++) {
            uint32_t af[2][4];
            ldsm4(af[0], sA + a_row * ROWB + ks * 32 + a_colb);
            ldsm4(af[1], sA + (a_row + 16) * ROWB + ks * 32 + a_colb);
            #pragma unroll
            for (int mi = 0; mi < 2; mi++)
                #pragma unroll
                for (int nt = 0; nt < 8; nt++)
                    mma_bf16(acc[mi][nt], af[mi], bf[nt][2 * ks], bf[nt][2 * ks + 1]);
        }
    }

    int gid = lane >> 2, tig = lane & 3;
    float bv[16];
    #pragma unroll
    for (int nt = 0; nt < 8; nt++) {
        int col = n0 + wn * 64 + nt * 8 + 2 * tig;
        bv[nt * 2]     = bias[col];
        bv[nt * 2 + 1] = bias[col + 1];
    }
    #pragma unroll
    for (int mi = 0; mi < 2; mi++) {
        int mrow = m0 + wm * 32 + mi * 16 + gid;
        #pragma unroll
        for (int nt = 0; nt < 8; nt++) {
            int col = n0 + wn * 64 + nt * 8 + 2 * tig;
            float v0 = acc[mi][nt][0] + bv[nt * 2];
            float v1 = acc[mi][nt][1] + bv[nt * 2 + 1];
            float v2 = acc[mi][nt][2] + bv[nt * 2];
            float v3 = acc[mi][nt][3] + bv[nt * 2 + 1];
            if (mode == 0) {
                float* C = (float*)Cout;
                float2 p0 = {v0, v1}, p1 = {v2, v3};
                *(float2*)&C[(size_t)mrow * Ntot + col]       = p0;
                *(float2*)&C[(size_t)(mrow + 8) * Ntot + col] = p1;
            } else {
                __nv_bfloat16* C = (__nv_bfloat16*)Cout;
                v0 = tanhf(v0); v1 = tanhf(v1); v2 = tanhf(v2); v3 = tanhf(v3);
                __nv_bfloat16 h0 = __float2bfloat16(v0), h1 = __float2bfloat16(v1);
                __nv_bfloat16 h2 = __float2bfloat16(v2), h3 = __float2bfloat16(v3);
                __nv_bfloat16 l0 = __float2bfloat16(v0 - __bfloat162float(h0));
                __nv_bfloat16 l1 = __float2bfloat16(v1 - __bfloat162float(h1));
                __nv_bfloat16 l2 = __float2bfloat16(v2 - __bfloat162float(h2));
                __nv_bfloat16 l3 = __float2bfloat16(v3 - __bfloat162float(h3));
                __nv_bfloat162 ph0 = {h0, h1}, ph1 = {h2, h3};
                __nv_bfloat162 pl0 = {l0, l1}, pl1 = {l2, l3};
                *(__nv_bfloat162*)&C[(size_t)mrow * 1024 + col]             = ph0;
                *(__nv_bfloat162*)&C[(size_t)mrow * 1024 + 512 + col]       = pl0;
                *(__nv_bfloat162*)&C[(size_t)(mrow + 8) * 1024 + col]       = ph1;
                *(__nv_bfloat162*)&C[(size_t)(mrow + 8) * 1024 + 512 + col] = pl1;
            }
        }
    }
}

// ---------------------------------------------------------------------------
// Persistent GRU scan: bulk-DMA h staging + 12 mma warps (384 threads).
//   gh[48x32] = 12 m16n8 tiles, ONE tile per warp -> 3 warps / SMSP, balanced.
//   e2 stores moved after the barrier arrive (overlap peer wait).
// ---------------------------------------------------------------------------
#define SC_STRIDE 520                            // bf16 elems/row -> 1040 B
#define SC_W_BYTES (96 * SC_STRIDE * 2)          // 99840
#define SC_H_BYTES (64 * SC_STRIDE * 2)          // 66560
#define SC_GH_F    (48 * 33)
#define SCAN_SMEM_BYTES (SC_W_BYTES + SC_H_BYTES + SC_GH_F * 4 + 256)

__global__ void __launch_bounds__(384, 1)
k_scan(const float* __restrict__ Whh, const float* __restrict__ bhh) {
    extern __shared__ __align__(16) char dynsm[];
    __nv_bfloat16* ws  = (__nv_bfloat16*)dynsm;
    __nv_bfloat16* hsb = (__nv_bfloat16*)(dynsm + SC_W_BYTES);
    float* gh  = (float*)(dynsm + SC_W_BYTES + SC_H_BYTES);
    float* bsh = gh + SC_GH_F;
    uint32_t ws_u = smem_u32(ws);
    uint32_t hs_u = smem_u32(hsb);
    uint32_t mbA = smem_u32(dynsm + SC_W_BYTES + SC_H_BYTES + SC_GH_F * 4 + 192);
    uint32_t mbB = mbA + 8;

    int tid = threadIdx.x, wid = tid >> 5, lane = tid & 31;
    int blk = blockIdx.x;
    int bg = blk >> 5, dg = blk & 31;
    int d0 = dg << 4, b0 = bg << 5;

    // Load W slice once, split into bf16 hi/lo plane rows.
    for (int i = tid; i < 48 * 512; i += 384) {
        int j = i >> 9, k = i & 511;            // j = gate*16 + dc
        int g = j >> 4, dc = j & 15;
        float w = Whh[(size_t)(g * 512 + d0 + dc) * 512 + k];
        __nv_bfloat16 hi = __float2bfloat16(w);
        __nv_bfloat16 lo = __float2bfloat16(w - __bfloat162float(hi));
        ws[j * SC_STRIDE + k]        = hi;
        ws[(48 + j) * SC_STRIDE + k] = lo;
    }
    if (tid < 48) bsh[tid] = bhh[(tid >> 4) * 512 + d0 + (tid & 15)];
    if (tid == 0) { mbar_init(mbA, 1); mbar_init(mbB, 1); }
    __syncthreads();

    int mt = wid >> 2, nt = wid & 3;            // one m16n8 tile per warp
    uint32_t aw_hi = ws_u + (uint32_t)((mt * 16 + (lane & 15)) * 1040)
                   + ((lane >> 4) << 4);
    uint32_t aw_lo = aw_hi + 48u * 1040u;
    uint32_t bh_hi = hs_u + (uint32_t)((nt * 8 + (lane & 7)) * 1040)
                   + ((lane >> 3) << 4);
    uint32_t bh_lo = bh_hi + 32u * 1040u;

    int p = 0;

    for (int t = 0; t < HALF_T; t++) {
        // prefetch gx gate values (overlaps DMA): outputs o = tid, tid+384
        float gxv[2][3];
        {
            int bi = tid >> 4, dc = tid & 15;
            size_t row = ((size_t)(b0 + bi) * 256 + t) * 1536;
            gxv[0][0] = __ldcg(g_gx + row + d0 + dc);
            gxv[0][1] = __ldcg(g_gx + row + 512 + d0 + dc);
            gxv[0][2] = __ldcg(g_gx + row + 1024 + d0 + dc);
            if (tid < 128) {
                int o = tid + 384;
                int bi2 = o >> 4, dc2 = o & 15;
                size_t row2 = ((size_t)(b0 + bi2) * 256 + t) * 1536;
                gxv[1][0] = __ldcg(g_gx + row2 + d0 + dc2);
                gxv[1][1] = __ldcg(g_gx + row2 + 512 + d0 + dc2);
                gxv[1][2] = __ldcg(g_gx + row2 + 1024 + d0 + dc2);
            }
        }

        // bulk-DMA stage h planes (hi block then lo block)
        if (tid == 0) {
            const __nv_bfloat16* src = g_h2 + ((size_t)p * 4 + bg) * HGRP;
            mbar_expect(mbA, 33280u);
            mbar_expect(mbB, 33280u);
            bulkcp(hs_u,          src,         33280u, mbA);
            bulkcp(hs_u + 33280u, src + 16640, 33280u, mbB);
        }
        mbar_wait(mbA, (uint32_t)(t & 1));      // hi plane visible

        // hi phase: (Whi + Wlo) x h_hi, lo DMA still in flight
        float acc[4] = {0.f, 0.f, 0.f, 0.f};
        #pragma unroll 4
        for (int k32 = 0; k32 < 16; k32++) {
            int kb = k32 << 6;
            uint32_t ah0[4], ah1[4], al0[4], al1[4], bf[4];
            ldsm4(ah0, aw_hi + kb);
            ldsm4(ah1, aw_hi + kb + 32);
            ldsm4(al0, aw_lo + kb);
            ldsm4(al1, aw_lo + kb + 32);
            ldsm4(bf, bh_hi + kb);
            mma_bf16(acc, ah0, bf[0], bf[1]);
            mma_bf16(acc, ah1, bf[2], bf[3]);
            mma_bf16(acc, al0, bf[0], bf[1]);
            mma_bf16(acc, al1, bf[2], bf[3]);
        }
        mbar_wait(mbB, (uint32_t)(t & 1));      // lo plane visible

        // lo phase: Whi x h_lo
        #pragma unroll 4
        for (int k32 = 0; k32 < 16; k32++) {
            int kb = k32 << 6;
            uint32_t bl[4], ah0[4], ah1[4];
            ldsm4(bl, bh_lo + kb);
            ldsm4(ah0, aw_hi + kb);
            ldsm4(ah1, aw_hi + kb + 32);
            mma_bf16(acc, ah0, bl[0], bl[1]);
            mma_bf16(acc, ah1, bl[2], bl[3]);
        }
        // write gh fragment (one tile per warp)
        {
            int r = lane >> 2, c = (lane & 3) << 1;
            int n = nt * 8 + c;
            int m = mt * 16 + r;
            gh[m * 33 + n]           = acc[0];
            gh[m * 33 + n + 1]       = acc[1];
            gh[(m + 8) * 33 + n]     = acc[2];
            gh[(m + 8) * 33 + n + 1] = acc[3];
        }
        __syncthreads();

        // epilogue: output o = tid (all), o = tid+384 (tid<128)
        __nv_bfloat16 ehi[2], elo[2];
        #pragma unroll
        for (int q = 0; q < 2; q++) {
            if (q == 0 || tid < 128) {
                int o = tid + q * 384;
                int bi = o >> 4, dc = o & 15;
                int d_a = d0 + dc;
                float ghr = gh[dc * 33 + bi]        + bsh[dc];
                float ghz = gh[(16 + dc) * 33 + bi] + bsh[16 + dc];
                float ghn = gh[(32 + dc) * 33 + bi] + bsh[32 + dc];
                float r = 1.0f / (1.0f + __expf(-(gxv[q][0] + ghr)));
                float z = 1.0f / (1.0f + __expf(-(gxv[q][1] + ghz)));
                float n = tanhf(gxv[q][2] + r * ghn);
                float hold = __bfloat162float(hsb[bi * SC_STRIDE + d_a])
                           + __bfloat162float(hsb[(32 + bi) * SC_STRIDE + d_a]);
                float hn = (1.0f - z) * n + z * hold;
                __nv_bfloat16 hi = __float2bfloat16(hn);
                __nv_bfloat16 lo = __float2bfloat16(hn - __bfloat162float(hi));
                ehi[q] = hi; elo[q] = lo;
                if (t < HALF_T - 1) {
                    size_t gb = ((size_t)(p ^ 1) * 4 + bg) * HGRP;
                    g_h2[gb + bi * HROW + d_a]         = hi;
                    g_h2[gb + 16640 + bi * HROW + d_a] = lo;
                }
            }
        }

        if (t < HALF_T - 1) {
            __threadfence();                     // drain h stores
            __syncthreads();
            if (tid == 0) atomicAdd(&g_ctr4[bg * 32], 1u);   // arrive
        }

        // e2 stores overlap the peer wait
        #pragma unroll
        for (int q = 0; q < 2; q++) {
            if (q == 0 || tid < 128) {
                int o = tid + q * 384;
                int bi = o >> 4, dc = o & 15;
                size_t erow = ((size_t)(b0 + bi) * 256 + t) * 1024;
                g_e2[erow + d0 + dc]       = ehi[q];
                g_e2[erow + 512 + d0 + dc] = elo[q];
            }
        }

        if (t < HALF_T - 1) {
            if (tid == 0) {
                unsigned target = (unsigned)(t + 1) * 32u;
                volatile unsigned* vc = &g_ctr4[bg * 32];
                while (*vc < target) { }
            }
            __syncthreads();
        }
        p ^= 1;
    }
}

// ---------------------------------------------------------------------------
// Fused head: out[m] = logsoftmax(f[m]) @ W_comb^T + b_comb
// ---------------------------------------------------------------------------
__global__ void __launch_bounds__(256)
k_final(const float* __restrict__ X, float* __restrict__ out) {
    __shared__ float Wc[NCLS * DD];
    __shared__ float ss[NCLS], bc[NCLS];
    int tid = threadIdx.x;
    for (int idx = tid; idx < NCLS * DD; idx += 256) Wc[idx] = g_Wc[idx];
    if (tid < NCLS) { ss[tid] = g_s[tid]; bc[tid] = g_bc[tid]; }
    __syncthreads();

    int w = tid >> 5, l = tid & 31;
    int m = (blockIdx.x << 3) + w;
    const float* xr = X + (size_t)m * DD;

    float f[16];
    #pragma unroll
    for (int i = 0; i < 16; i++) f[i] = xr[i * 32 + l];

    float mx = f[0];
    #pragma unroll
    for (int i = 1; i < 16; i++) mx = fmaxf(mx, f[i]);
    #pragma unroll
    for (int off = 16; off > 0; off >>= 1)
        mx = fmaxf(mx, __shfl_xor_sync(0xffffffffu, mx, off));

    float se = 0.0f;
    #pragma unroll
    for (int i = 0; i < 16; i++) se += __expf(f[i] - mx);
    #pragma unroll
    for (int off = 16; off > 0; off >>= 1)
        se += __shfl_xor_sync(0xffffffffu, se, off);
    float c = mx + __logf(se);

    #pragma unroll
    for (int n = 0; n < NCLS; n++) {
        float dot = 0.0f;
        const float* wr = Wc + n * DD;
        #pragma unroll
        for (int i = 0; i < 16; i++) dot += f[i] * wr[i * 32 + l];
        #pragma unroll
        for (int off = 16; off > 0; off >>= 1)
            dot += __shfl_xor_sync(0xffffffffu, dot, off);
        if (l == 0) out[m * NCLS + n] = dot - c * ss[n] + bc[n];
    }
}

// ---------------------------------------------------------------------------
// kernel_launch — ordered so k_scan is launch index 5 (ncu -s 5 -c 1 target)
// ---------------------------------------------------------------------------
extern "C" void kernel_launch(void* const* d_in, const int* in_sizes, int n_in,
                              void* d_out, int out_size) {
    (void)in_sizes; (void)out_size;
    if (n_in < 17) return;
    const float* x0     = (const float*)d_in[0];
    const float* W_ih   = (const float*)d_in[3];
    const float* W_hh   = (const float*)d_in[4];
    const float* b_ih   = (const float*)d_in[5];
    const float* b_hh   = (const float*)d_in[6];
    const float* W1     = (const float*)d_in[7];
    const float* bb1    = (const float*)d_in[8];
    const float* W2     = (const float*)d_in[9];
    const float* bb2    = (const float*)d_in[10];
    const float* W3     = (const float*)d_in[11];
    const float* bb3    = (const float*)d_in[12];
    const float* W_half = (const float*)d_in[13];
    const float* b_half = (const float*)d_in[14];
    const float* W_out  = (const float*)d_in[15];
    const float* b_out  = (const float*)d_in[16];
    float* out = (float*)d_out;

    float *gx, *x3;
    __nv_bfloat16 *A0, *e2, *x1b, *x2b, *Wih2, *W12, *W22, *W32;
    cudaGetSymbolAddress((void**)&gx,   g_gx);
    cudaGetSymbolAddress((void**)&x3,   g_x3);
    cudaGetSymbolAddress((void**)&A0,   g_A0);
    cudaGetSymbolAddress((void**)&e2,   g_e2);
    cudaGetSymbolAddress((void**)&x1b,  g_x1b);
    cudaGetSymbolAddress((void**)&x2b,  g_x2b);
    cudaGetSymbolAddress((void**)&Wih2, g_Wih2);
    cudaGetSymbolAddress((void**)&W12,  g_W12);
    cudaGetSymbolAddress((void**)&W22,  g_W22);
    cudaGetSymbolAddress((void**)&W32,  g_W32);

    cudaFuncSetAttribute(k_scan, cudaFuncAttributeMaxDynamicSharedMemorySize,
                         SCAN_SMEM_BYTES);
    cudaFuncSetAttribute(k_mma_gemm, cudaFuncAttributeMaxDynamicSharedMemorySize,
                         GEMM_SMEM);

    // 0,1: input/weight splits needed by gx GEMM
    k_split<<<(MROWS * 128) / 256, 256>>>(x0, A0, MROWS, 1);
    k_split<<<(1536 * 128) / 256, 256>>>(W_ih, Wih2, 1536, 0);
    // 2: init h planes + barrier counters
    k_init<<<520, 256>>>();
    // 3: gx = x0 @ W_ih^T + b_ih   [32768 x 1536]  (128x128 tiles)
    k_mma_gemm<<<256 * 12, 256, GEMM_SMEM>>>(A0, Wih2, b_ih, gx, 1536, 12, 0);
    // 4: head fold (independent)
    k_prep1<<<14, 256>>>(W_half, W_out);
    // 5: GRU scan (PROFILED)
    k_scan<<<128, 384, SCAN_SMEM_BYTES>>>(W_hh, b_hh);
    // 6: head fold part 2
    k_prep2<<<1, 256>>>(W_out, b_half, b_out);
    // 7-9: FFN weight splits
    k_split<<<(512 * 128) / 256, 256>>>(W1, W12, 512, 0);
    k_split<<<(512 * 128) / 256, 256>>>(W2, W22, 512, 0);
    k_split<<<(512 * 128) / 256, 256>>>(W3, W32, 512, 0);
    // 10-12: FFN (128x128 tiles)
    k_mma_gemm<<<256 * 4, 256, GEMM_SMEM>>>(e2,  W12, bb1, x1b, 512, 4, 1);
    k_mma_gemm<<<256 * 4, 256, GEMM_SMEM>>>(x1b, W22, bb2, x2b, 512, 4, 1);
    k_mma_gemm<<<256 * 4, 256, GEMM_SMEM>>>(x2b, W32, bb3, x3,  512, 4, 0);
    // 13: fused log_softmax + combined classifier head
    k_final<<<MROWS / 8, 256>>>(x3, out);
}

// round 13
// speedup vs baseline: 1.2001x; 1.2001x over previous
#include <cuda_runtime.h>
#include <cuda_bf16.h>
#include <cstddef>
#include <cstdint>

// Problem constants
#define BB     128
#define TT     512
#define HALF_T 256
#define DD     512
#define NCLS   7
#define MROWS  (BB * HALF_T)   // 32768 rows fed to FFN / head

typedef unsigned long long ull;

// ---------------------------------------------------------------------------
// mma.sync / ldmatrix / cp.async / bulk-DMA helpers (baseline PTX, sm_100-safe)
// ---------------------------------------------------------------------------
__device__ __forceinline__ uint32_t smem_u32(const void* p) {
    uint32_t a;
    asm("{ .reg .u64 t; cvta.to.shared.u64 t, %1; cvt.u32.u64 %0, t; }"
        : "=r"(a) : "l"(p));
    return a;
}
__device__ __forceinline__ void ldsm4(uint32_t* r, uint32_t addr) {
    asm volatile("ldmatrix.sync.aligned.m8n8.x4.shared.b16 {%0,%1,%2,%3}, [%4];"
        : "=r"(r[0]), "=r"(r[1]), "=r"(r[2]), "=r"(r[3]) : "r"(addr));
}
__device__ __forceinline__ void mma_bf16(float* d, const uint32_t* a,
                                         uint32_t b0, uint32_t b1) {
    asm volatile("mma.sync.aligned.m16n8k16.row.col.f32.bf16.bf16.f32 "
        "{%0,%1,%2,%3}, {%4,%5,%6,%7}, {%8,%9}, {%0,%1,%2,%3};"
        : "+f"(d[0]), "+f"(d[1]), "+f"(d[2]), "+f"(d[3])
        : "r"(a[0]), "r"(a[1]), "r"(a[2]), "r"(a[3]), "r"(b0), "r"(b1));
}
__device__ __forceinline__ void cpasync16(uint32_t dst, const void* src) {
    asm volatile("cp.async.cg.shared.global [%0], [%1], 16;"
                 :: "r"(dst), "l"(src));
}
#define CP_COMMIT() asm volatile("cp.async.commit_group;" ::: "memory")

// bulk DMA: gmem -> smem, completion via mbarrier complete_tx
__device__ __forceinline__ void bulkcp(uint32_t dst, const void* src,
                                       uint32_t bytes, uint32_t mbar) {
    asm volatile(
        "cp.async.bulk.shared::cluster.global.mbarrier::complete_tx::bytes "
        "[%0], [%1], %2, [%3];"
        :: "r"(dst), "l"(src), "r"(bytes), "r"(mbar) : "memory");
}
__device__ __forceinline__ void mbar_init(uint32_t mbar, uint32_t cnt) {
    asm volatile("mbarrier.init.shared.b64 [%0], %1;"
                 :: "r"(mbar), "r"(cnt) : "memory");
}
__device__ __forceinline__ void mbar_expect(uint32_t mbar, uint32_t bytes) {
    asm volatile("mbarrier.arrive.expect_tx.shared.b64 _, [%0], %1;"
                 :: "r"(mbar), "r"(bytes) : "memory");
}
__device__ __forceinline__ void mbar_wait(uint32_t mbar, uint32_t parity) {
    asm volatile("{\n\t.reg .pred P;\n\tWL%=:\n\t"
                 "mbarrier.try_wait.parity.acquire.cta.shared::cta.b64 P, [%0], %1;\n\t"
                 "@!P bra WL%=;\n\t}" :: "r"(mbar), "r"(parity) : "memory");
}

// ---------------------------------------------------------------------------
// Device scratch
// ---------------------------------------------------------------------------
__device__ float g_gx[MROWS * 1536];             // input projections (fp32)
__device__ float g_x3[MROWS * DD];               // FFN layer-3 output (fp32)
__device__ __nv_bfloat16 g_A0 [MROWS * 1024];    // x0 split planes (hi|lo)
__device__ __nv_bfloat16 g_e2 [MROWS * 1024];    // emotions split planes
__device__ __nv_bfloat16 g_x1b[MROWS * 1024];
__device__ __nv_bfloat16 g_x2b[MROWS * 1024];
__device__ __nv_bfloat16 g_Wih2[1536 * 1024];    // weight split planes
__device__ __nv_bfloat16 g_W12 [512 * 1024];
__device__ __nv_bfloat16 g_W22 [512 * 1024];
__device__ __nv_bfloat16 g_W32 [512 * 1024];
// GRU h planes, padded layout for bulk DMA:
// [2 bufs][4 groups][2 planes][32 batches][520]  (row = plane*32+batch)
#define HROW 520
#define HGRP (2 * 32 * HROW)                     // 33280 elems / 66560 B
__device__ __nv_bfloat16 g_h2[2 * 4 * HGRP];
__device__ float g_Wc[NCLS * DD];
__device__ float g_s [NCLS];
__device__ float g_bc[NCLS];
__device__ unsigned g_ctr4[4 * 32];              // barrier counters, 128B apart

// ---------------------------------------------------------------------------
// Init: zero h planes buffer 0 + barrier counters (reset every graph replay)
// ---------------------------------------------------------------------------
__global__ void k_init() {
    int idx = blockIdx.x * 256 + threadIdx.x;   // 520 blocks = 133120 threads
    if (idx < 4 * HGRP / 2) {
        ((__nv_bfloat162*)g_h2)[idx] = __nv_bfloat162{__nv_bfloat16(0.f),
                                                      __nv_bfloat16(0.f)};
    }
    if (idx < 4) g_ctr4[idx * 32] = 0u;
}

// ---------------------------------------------------------------------------
// prep1/prep2: fold log_softmax + classifier head
// ---------------------------------------------------------------------------
__global__ void k_prep1(const float* __restrict__ W_half,
                        const float* __restrict__ W_out) {
    int idx = blockIdx.x * 256 + threadIdx.x;
    if (idx >= NCLS * DD) return;
    int n = idx / DD, k = idx % DD;
    float s = 0.0f;
    for (int j = 0; j < 256; j++)
        s += W_out[n * 256 + j] * W_half[j * DD + k];
    g_Wc[idx] = s;
}
__global__ void k_prep2(const float* __restrict__ W_out,
                        const float* __restrict__ b_half,
                        const float* __restrict__ b_out) {
    int tid = threadIdx.x;
    int w = tid >> 5, l = tid & 31;
    if (w < NCLS) {
        float s = 0.0f;
        #pragma unroll
        for (int i = 0; i < 16; i++) s += g_Wc[w * DD + i * 32 + l];
        #pragma unroll
        for (int off = 16; off > 0; off >>= 1)
            s += __shfl_xor_sync(0xffffffffu, s, off);
        if (l == 0) g_s[w] = s;
    }
    if (tid < NCLS) {
        float b = b_out[tid];
        for (int j = 0; j < 256; j++)
            b += W_out[tid * 256 + j] * b_half[j];
        g_bc[tid] = b;
    }
}

// ---------------------------------------------------------------------------
// k_split: fp32 [rows,512] -> bf16 hi/lo planes [rows,1024]
// ---------------------------------------------------------------------------
__global__ void k_split(const float* __restrict__ src,
                        __nv_bfloat16* __restrict__ dst,
                        int nrows, int perm) {
    int idx = blockIdx.x * 256 + threadIdx.x;
    if (idx >= nrows * 128) return;
    int r = idx >> 7, c4 = (idx & 127) << 2;
    size_t so = perm ? ((size_t)((r >> 8) * 512 + (r & 255)) * 512)
                     : ((size_t)r * 512);
    float4 v = *(const float4*)(src + so + c4);
    __nv_bfloat16 h[4], lo[4];
    float vv[4] = {v.x, v.y, v.z, v.w};
    #pragma unroll
    for (int i = 0; i < 4; i++) {
        h[i] = __float2bfloat16(vv[i]);
        lo[i] = __float2bfloat16(vv[i] - __bfloat162float(h[i]));
    }
    *(ull*)(dst + (size_t)r * 1024 + c4)       = *(ull*)h;
    *(ull*)(dst + (size_t)r * 1024 + 512 + c4) = *(ull*)lo;
}

// ---------------------------------------------------------------------------
// mma.sync bf16-split GEMM, 128x128 tile, 3-stage cp.async pipeline
// (exact R10 config — proven 549 us on gx).
// ---------------------------------------------------------------------------
#define ROWB 80          // padded smem row: 32 bf16 (64B) + 16B pad
#define BUFB (128 * ROWB)
#define NST  3
#define GEMM_SMEM (2 * NST * BUFB)   // 61440

__global__ void __launch_bounds__(256, 2)
k_mma_gemm(const __nv_bfloat16* __restrict__ A,
           const __nv_bfloat16* __restrict__ Bw,
           const float* __restrict__ bias,
           void* __restrict__ Cout,
           int Ntot, int n_tiles, int mode) {
    extern __shared__ __align__(16) char smc[];
    uint32_t sbase = smem_u32(smc);
    int tid = threadIdx.x, wid = tid >> 5, lane = tid & 31;
    int m0 = (blockIdx.x / n_tiles) << 7;
    int n0 = (blockIdx.x % n_tiles) << 7;

    int sr = tid >> 2;
    int sc = tid & 3;

    float acc[2][8][4];
    #pragma unroll
    for (int i = 0; i < 2; i++)
        #pragma unroll
        for (int j = 0; j < 8; j++)
            #pragma unroll
            for (int q = 0; q < 4; q++) acc[i][j][q] = 0.0f;

    auto issue = [&](int c) {
        int seg = c >> 4, kofs = (c & 15) << 5;
        int asel = (seg == 1) ? 512 : 0;
        int bsel = (seg == 2) ? 512 : 0;
        const __nv_bfloat16* Ag = A + (size_t)m0 * 1024 + asel + kofs;
        const __nv_bfloat16* Bg = Bw + (size_t)n0 * 1024 + bsel + kofs;
        int buf = c % NST;
        uint32_t da = sbase + (uint32_t)buf * BUFB;
        uint32_t db = sbase + (uint32_t)(NST + buf) * BUFB;
        cpasync16(da + sr * ROWB + sc * 16,        Ag + (size_t)sr * 1024 + sc * 8);
        cpasync16(da + (sr + 64) * ROWB + sc * 16, Ag + (size_t)(sr + 64) * 1024 + sc * 8);
        cpasync16(db + sr * ROWB + sc * 16,        Bg + (size_t)sr * 1024 + sc * 8);
        cpasync16(db + (sr + 64) * ROWB + sc * 16, Bg + (size_t)(sr + 64) * 1024 + sc * 8);
        CP_COMMIT();
    };

    issue(0);
    issue(1);

    int wm = wid & 3;
    int wn = wid >> 2;
    uint32_t a_row  = (uint32_t)(wm * 32 + (lane & 15));
    uint32_t a_colb = (uint32_t)((lane >> 4) * 16);
    uint32_t b_row  = (uint32_t)(wn * 64 + (lane & 7));
    uint32_t b_colb = (uint32_t)((lane >> 3) * 16);

    for (int c = 0; c < 48; c++) {
        if (c < 47) asm volatile("cp.async.wait_group 1;" ::: "memory");
        else        asm volatile("cp.async.wait_group 0;" ::: "memory");
        __syncthreads();
        if (c + 2 < 48) issue(c + 2);

        int buf = c % NST;
        uint32_t sA = sbase + (uint32_t)buf * BUFB;
        uint32_t sB = sbase + (uint32_t)(NST + buf) * BUFB;

        uint32_t bf[8][4];
        #pragma unroll
        for (int nt = 0; nt < 8; nt++)
            ldsm4(bf[nt], sB + (b_row + nt * 8) * ROWB + b_colb);

        #pragma unroll
        for (int ks = 0; ks < 2; ks++) {
            uint32_t af[2][4];
            ldsm4(af[0], sA + a_row * ROWB + ks * 32 + a_colb);
            ldsm4(af[1], sA + (a_row + 16) * ROWB + ks * 32 + a_colb);
            #pragma unroll
            for (int mi = 0; mi < 2; mi++)
                #pragma unroll
                for (int nt = 0; nt < 8; nt++)
                    mma_bf16(acc[mi][nt], af[mi], bf[nt][2 * ks], bf[nt][2 * ks + 1]);
        }
    }

    int gid = lane >> 2, tig = lane & 3;
    float bv[16];
    #pragma unroll
    for (int nt = 0; nt < 8; nt++) {
        int col = n0 + wn * 64 + nt * 8 + 2 * tig;
        bv[nt * 2]     = bias[col];
        bv[nt * 2 + 1] = bias[col + 1];
    }
    #pragma unroll
    for (int mi = 0; mi < 2; mi++) {
        int mrow = m0 + wm * 32 + mi * 16 + gid;
        #pragma unroll
        for (int nt = 0; nt < 8; nt++) {
            int col = n0 + wn * 64 + nt * 8 + 2 * tig;
            float v0 = acc[mi][nt][0] + bv[nt * 2];
            float v1 = acc[mi][nt][1] + bv[nt * 2 + 1];
            float v2 = acc[mi][nt][2] + bv[nt * 2];
            float v3 = acc[mi][nt][3] + bv[nt * 2 + 1];
            if (mode == 0) {
                float* C = (float*)Cout;
                float2 p0 = {v0, v1}, p1 = {v2, v3};
                *(float2*)&C[(size_t)mrow * Ntot + col]       = p0;
                *(float2*)&C[(size_t)(mrow + 8) * Ntot + col] = p1;
            } else {
                __nv_bfloat16* C = (__nv_bfloat16*)Cout;
                v0 = tanhf(v0); v1 = tanhf(v1); v2 = tanhf(v2); v3 = tanhf(v3);
                __nv_bfloat16 h0 = __float2bfloat16(v0), h1 = __float2bfloat16(v1);
                __nv_bfloat16 h2 = __float2bfloat16(v2), h3 = __float2bfloat16(v3);
                __nv_bfloat16 l0 = __float2bfloat16(v0 - __bfloat162float(h0));
                __nv_bfloat16 l1 = __float2bfloat16(v1 - __bfloat162float(h1));
                __nv_bfloat16 l2 = __float2bfloat16(v2 - __bfloat162float(h2));
                __nv_bfloat16 l3 = __float2bfloat16(v3 - __bfloat162float(h3));
                __nv_bfloat162 ph0 = {h0, h1}, ph1 = {h2, h3};
                __nv_bfloat162 pl0 = {l0, l1}, pl1 = {l2, l3};
                *(__nv_bfloat162*)&C[(size_t)mrow * 1024 + col]             = ph0;
                *(__nv_bfloat162*)&C[(size_t)mrow * 1024 + 512 + col]       = pl0;
                *(__nv_bfloat162*)&C[(size_t)(mrow + 8) * 1024 + col]       = ph1;
                *(__nv_bfloat162*)&C[(size_t)(mrow + 8) * 1024 + 512 + col] = pl1;
            }
        }
    }
}

// ---------------------------------------------------------------------------
// Persistent GRU scan (R10 structure) + W-hi fragments hoisted to registers.
//   ldsm per step per mma-warp: 160 -> 96 (smem-BW bound relieved).
// ---------------------------------------------------------------------------
#define SC_STRIDE 520                            // bf16 elems/row -> 1040 B
#define SC_W_BYTES (96 * SC_STRIDE * 2)          // 99840
#define SC_H_BYTES (64 * SC_STRIDE * 2)          // 66560
#define SC_GH_F    (48 * 33)
#define SCAN_SMEM_BYTES (SC_W_BYTES + SC_H_BYTES + SC_GH_F * 4 + 256)

__global__ void __launch_bounds__(256, 1)
k_scan(const float* __restrict__ Whh, const float* __restrict__ bhh) {
    extern __shared__ __align__(16) char dynsm[];
    __nv_bfloat16* ws  = (__nv_bfloat16*)dynsm;
    __nv_bfloat16* hsb = (__nv_bfloat16*)(dynsm + SC_W_BYTES);
    float* gh  = (float*)(dynsm + SC_W_BYTES + SC_H_BYTES);
    float* bsh = gh + SC_GH_F;
    uint32_t ws_u = smem_u32(ws);
    uint32_t hs_u = smem_u32(hsb);
    uint32_t mbA = smem_u32(dynsm + SC_W_BYTES + SC_H_BYTES + SC_GH_F * 4 + 192);
    uint32_t mbB = mbA + 8;

    int tid = threadIdx.x, wid = tid >> 5, lane = tid & 31;
    int blk = blockIdx.x;
    int bg = blk >> 5, dg = blk & 31;
    int d0 = dg << 4, b0 = bg << 5;

    // Load W slice once, split into bf16 hi/lo plane rows.
    for (int i = tid; i < 48 * 512; i += 256) {
        int j = i >> 9, k = i & 511;            // j = gate*16 + dc
        int g = j >> 4, dc = j & 15;
        float w = Whh[(size_t)(g * 512 + d0 + dc) * 512 + k];
        __nv_bfloat16 hi = __float2bfloat16(w);
        __nv_bfloat16 lo = __float2bfloat16(w - __bfloat162float(hi));
        ws[j * SC_STRIDE + k]        = hi;
        ws[(48 + j) * SC_STRIDE + k] = lo;
    }
    if (tid < 48) bsh[tid] = bhh[(tid >> 4) * 512 + d0 + (tid & 15)];
    if (tid == 0) { mbar_init(mbA, 1); mbar_init(mbB, 1); }
    __syncthreads();

    int mt = wid % 3, nh = wid / 3;             // mma mapping (wid < 6)
    uint32_t aw_hi = ws_u + (uint32_t)((mt * 16 + (lane & 15)) * 1040)
                   + ((lane >> 4) << 4);
    uint32_t aw_lo = aw_hi + 48u * 1040u;
    uint32_t bh_hi = hs_u + (uint32_t)((nh * 16 + (lane & 7)) * 1040)
                   + ((lane >> 3) << 4);
    uint32_t bh_lo = bh_hi + 32u * 1040u;

    // Hoist W-hi fragments into registers (loop-invariant across 256 steps).
    uint32_t ahr[16][2][4];
    if (wid < 6) {
        #pragma unroll
        for (int k32 = 0; k32 < 16; k32++) {
            ldsm4(ahr[k32][0], aw_hi + (k32 << 6));
            ldsm4(ahr[k32][1], aw_hi + (k32 << 6) + 32);
        }
    }

    int bi_a = tid >> 4;                        // epilogue: batches bi_a, +16
    int dc_a = tid & 15;
    int d_a = d0 + dc_a;
    int p = 0;

    for (int t = 0; t < HALF_T; t++) {
        // prefetch gx gate values (overlaps DMA)
        size_t rowA = ((size_t)(b0 + bi_a) * 256 + t) * 1536;
        size_t rowB = ((size_t)(b0 + bi_a + 16) * 256 + t) * 1536;
        float gxrA = __ldcg(g_gx + rowA + d_a);
        float gxzA = __ldcg(g_gx + rowA + 512 + d_a);
        float gxnA = __ldcg(g_gx + rowA + 1024 + d_a);
        float gxrB = __ldcg(g_gx + rowB + d_a);
        float gxzB = __ldcg(g_gx + rowB + 512 + d_a);
        float gxnB = __ldcg(g_gx + rowB + 1024 + d_a);

        // bulk-DMA stage h planes (hi block then lo block)
        if (tid == 0) {
            const __nv_bfloat16* src = g_h2 + ((size_t)p * 4 + bg) * HGRP;
            mbar_expect(mbA, 33280u);
            mbar_expect(mbB, 33280u);
            bulkcp(hs_u,          src,         33280u, mbA);
            bulkcp(hs_u + 33280u, src + 16640, 33280u, mbB);
        }
        mbar_wait(mbA, (uint32_t)(t & 1));      // hi plane visible

        // hi phase: (Whi + Wlo) x h_hi, lo DMA still in flight
        float acc[2][4];
        if (wid < 6) {
            #pragma unroll
            for (int nt = 0; nt < 2; nt++)
                #pragma unroll
                for (int q = 0; q < 4; q++) acc[nt][q] = 0.0f;
            #pragma unroll
            for (int k32 = 0; k32 < 16; k32++) {
                int kb = k32 << 6;
                uint32_t al0[4], al1[4], bf0[4], bf1[4];
                ldsm4(al0, aw_lo + kb);
                ldsm4(al1, aw_lo + kb + 32);
                ldsm4(bf0, bh_hi + kb);
                ldsm4(bf1, bh_hi + kb + 8 * 1040);
                mma_bf16(acc[0], ahr[k32][0], bf0[0], bf0[1]);
                mma_bf16(acc[1], ahr[k32][0], bf1[0], bf1[1]);
                mma_bf16(acc[0], ahr[k32][1], bf0[2], bf0[3]);
                mma_bf16(acc[1], ahr[k32][1], bf1[2], bf1[3]);
                mma_bf16(acc[0], al0, bf0[0], bf0[1]);
                mma_bf16(acc[1], al0, bf1[0], bf1[1]);
                mma_bf16(acc[0], al1, bf0[2], bf0[3]);
                mma_bf16(acc[1], al1, bf1[2], bf1[3]);
            }
        }
        mbar_wait(mbB, (uint32_t)(t & 1));      // lo plane visible

        if (wid < 6) {
            #pragma unroll
            for (int k32 = 0; k32 < 16; k32++) {
                int kb = k32 << 6;
                uint32_t bl0[4], bl1[4];
                ldsm4(bl0, bh_lo + kb);
                ldsm4(bl1, bh_lo + kb + 8 * 1040);
                mma_bf16(acc[0], ahr[k32][0], bl0[0], bl0[1]);
                mma_bf16(acc[1], ahr[k32][0], bl1[0], bl1[1]);
                mma_bf16(acc[0], ahr[k32][1], bl0[2], bl0[3]);
                mma_bf16(acc[1], ahr[k32][1], bl1[2], bl1[3]);
            }
            // write gh fragments
            int r = lane >> 2, c = (lane & 3) << 1;
            #pragma unroll
            for (int nt = 0; nt < 2; nt++) {
                int n = nh * 16 + nt * 8 + c;
                int m = mt * 16 + r;
                gh[m * 33 + n]           = acc[nt][0];
                gh[m * 33 + n + 1]       = acc[nt][1];
                gh[(m + 8) * 33 + n]     = acc[nt][2];
                gh[(m + 8) * 33 + n + 1] = acc[nt][3];
            }
        }
        __syncthreads();

        // epilogue: 2 outputs per thread
        #pragma unroll
        for (int half = 0; half < 2; half++) {
            int bi = bi_a + (half << 4);
            float gxr = half ? gxrB : gxrA;
            float gxz = half ? gxzB : gxzA;
            float gxn = half ? gxnB : gxnA;
            float ghr = gh[dc_a * 33 + bi]        + bsh[dc_a];
            float ghz = gh[(16 + dc_a) * 33 + bi] + bsh[16 + dc_a];
            float ghn = gh[(32 + dc_a) * 33 + bi] + bsh[32 + dc_a];
            float r = 1.0f / (1.0f + __expf(-(gxr + ghr)));
            float z = 1.0f / (1.0f + __expf(-(gxz + ghz)));
            float n = tanhf(gxn + r * ghn);
            float hold = __bfloat162float(hsb[bi * SC_STRIDE + d_a])
                       + __bfloat162float(hsb[(32 + bi) * SC_STRIDE + d_a]);
            float hn = (1.0f - z) * n + z * hold;
            int big = b0 + bi;
            __nv_bfloat16 hi = __float2bfloat16(hn);
            __nv_bfloat16 lo = __float2bfloat16(hn - __bfloat162float(hi));
            if (t < HALF_T - 1) {
                size_t gb = ((size_t)(p ^ 1) * 4 + bg) * HGRP;
                g_h2[gb + bi * HROW + d_a]         = hi;
                g_h2[gb + 16640 + bi * HROW + d_a] = lo;
            }
            size_t erow = ((size_t)big * 256 + t) * 1024;
            g_e2[erow + d_a]       = hi;
            g_e2[erow + 512 + d_a] = lo;
        }

        // per-batch-group grid barrier (skipped on the final step)
        if (t < HALF_T - 1) {
            __threadfence();
            __syncthreads();
            if (tid == 0) {
                unsigned target = (unsigned)(t + 1) * 32u;
                atomicAdd(&g_ctr4[bg * 32], 1u);
                volatile unsigned* vc = &g_ctr4[bg * 32];
                while (*vc < target) { }
            }
            __syncthreads();
        }
        p ^= 1;
    }
}

// ---------------------------------------------------------------------------
// Fused head: out[m] = logsoftmax(f[m]) @ W_comb^T + b_comb
// ---------------------------------------------------------------------------
__global__ void __launch_bounds__(256)
k_final(const float* __restrict__ X, float* __restrict__ out) {
    __shared__ float Wc[NCLS * DD];
    __shared__ float ss[NCLS], bc[NCLS];
    int tid = threadIdx.x;
    for (int idx = tid; idx < NCLS * DD; idx += 256) Wc[idx] = g_Wc[idx];
    if (tid < NCLS) { ss[tid] = g_s[tid]; bc[tid] = g_bc[tid]; }
    __syncthreads();

    int w = tid >> 5, l = tid & 31;
    int m = (blockIdx.x << 3) + w;
    const float* xr = X + (size_t)m * DD;

    float f[16];
    #pragma unroll
    for (int i = 0; i < 16; i++) f[i] = xr[i * 32 + l];

    float mx = f[0];
    #pragma unroll
    for (int i = 1; i < 16; i++) mx = fmaxf(mx, f[i]);
    #pragma unroll
    for (int off = 16; off > 0; off >>= 1)
        mx = fmaxf(mx, __shfl_xor_sync(0xffffffffu, mx, off));

    float se = 0.0f;
    #pragma unroll
    for (int i = 0; i < 16; i++) se += __expf(f[i] - mx);
    #pragma unroll
    for (int off = 16; off > 0; off >>= 1)
        se += __shfl_xor_sync(0xffffffffu, se, off);
    float c = mx + __logf(se);

    #pragma unroll
    for (int n = 0; n < NCLS; n++) {
        float dot = 0.0f;
        const float* wr = Wc + n * DD;
        #pragma unroll
        for (int i = 0; i < 16; i++) dot += f[i] * wr[i * 32 + l];
        #pragma unroll
        for (int off = 16; off > 0; off >>= 1)
            dot += __shfl_xor_sync(0xffffffffu, dot, off);
        if (l == 0) out[m * NCLS + n] = dot - c * ss[n] + bc[n];
    }
}

// ---------------------------------------------------------------------------
// kernel_launch — ordered so k_scan is launch index 5 (ncu -s 5 -c 1 target)
// ---------------------------------------------------------------------------
extern "C" void kernel_launch(void* const* d_in, const int* in_sizes, int n_in,
                              void* d_out, int out_size) {
    (void)in_sizes; (void)out_size;
    if (n_in < 17) return;
    const float* x0     = (const float*)d_in[0];
    const float* W_ih   = (const float*)d_in[3];
    const float* W_hh   = (const float*)d_in[4];
    const float* b_ih   = (const float*)d_in[5];
    const float* b_hh   = (const float*)d_in[6];
    const float* W1     = (const float*)d_in[7];
    const float* bb1    = (const float*)d_in[8];
    const float* W2     = (const float*)d_in[9];
    const float* bb2    = (const float*)d_in[10];
    const float* W3     = (const float*)d_in[11];
    const float* bb3    = (const float*)d_in[12];
    const float* W_half = (const float*)d_in[13];
    const float* b_half = (const float*)d_in[14];
    const float* W_out  = (const float*)d_in[15];
    const float* b_out  = (const float*)d_in[16];
    float* out = (float*)d_out;

    float *gx, *x3;
    __nv_bfloat16 *A0, *e2, *x1b, *x2b, *Wih2, *W12, *W22, *W32;
    cudaGetSymbolAddress((void**)&gx,   g_gx);
    cudaGetSymbolAddress((void**)&x3,   g_x3);
    cudaGetSymbolAddress((void**)&A0,   g_A0);
    cudaGetSymbolAddress((void**)&e2,   g_e2);
    cudaGetSymbolAddress((void**)&x1b,  g_x1b);
    cudaGetSymbolAddress((void**)&x2b,  g_x2b);
    cudaGetSymbolAddress((void**)&Wih2, g_Wih2);
    cudaGetSymbolAddress((void**)&W12,  g_W12);
    cudaGetSymbolAddress((void**)&W22,  g_W22);
    cudaGetSymbolAddress((void**)&W32,  g_W32);

    cudaFuncSetAttribute(k_scan, cudaFuncAttributeMaxDynamicSharedMemorySize,
                         SCAN_SMEM_BYTES);
    cudaFuncSetAttribute(k_mma_gemm, cudaFuncAttributeMaxDynamicSharedMemorySize,
                         GEMM_SMEM);

    // 0,1: input/weight splits needed by gx GEMM
    k_split<<<(MROWS * 128) / 256, 256>>>(x0, A0, MROWS, 1);
    k_split<<<(1536 * 128) / 256, 256>>>(W_ih, Wih2, 1536, 0);
    // 2: init h planes + barrier counters
    k_init<<<520, 256>>>();
    // 3: gx = x0 @ W_ih^T + b_ih   [32768 x 1536]  (128x128 tiles)
    k_mma_gemm<<<256 * 12, 256, GEMM_SMEM>>>(A0, Wih2, b_ih, gx, 1536, 12, 0);
    // 4: head fold (independent)
    k_prep1<<<14, 256>>>(W_half, W_out);
    // 5: GRU scan (PROFILED)
    k_scan<<<128, 256, SCAN_SMEM_BYTES>>>(W_hh, b_hh);
    // 6: head fold part 2
    k_prep2<<<1, 256>>>(W_out, b_half, b_out);
    // 7-9: FFN weight splits
    k_split<<<(512 * 128) / 256, 256>>>(W1, W12, 512, 0);
    k_split<<<(512 * 128) / 256, 256>>>(W2, W22, 512, 0);
    k_split<<<(512 * 128) / 256, 256>>>(W3, W32, 512, 0);
    // 10-12: FFN (128x128 tiles)
    k_mma_gemm<<<256 * 4, 256, GEMM_SMEM>>>(e2,  W12, bb1, x1b, 512, 4, 1);
    k_mma_gemm<<<256 * 4, 256, GEMM_SMEM>>>(x1b, W22, bb2, x2b, 512, 4, 1);
    k_mma_gemm<<<256 * 4, 256, GEMM_SMEM>>>(x2b, W32, bb3, x3,  512, 4, 0);
    // 13: fused log_softmax + combined classifier head
    k_final<<<MROWS / 8, 256>>>(x3, out);
}

// round 14
// speedup vs baseline: 1.2737x; 1.0613x over previous
#include <cuda_runtime.h>
#include <cuda_bf16.h>
#include <cstddef>
#include <cstdint>

// Problem constants
#define BB     128
#define TT     512
#define HALF_T 256
#define DD     512
#define NCLS   7
#define MROWS  (BB * HALF_T)   // 32768 rows fed to FFN / head

typedef unsigned long long ull;

// ---------------------------------------------------------------------------
// mma.sync / ldmatrix / cp.async / bulk-DMA helpers (baseline PTX, sm_100-safe)
// ---------------------------------------------------------------------------
__device__ __forceinline__ uint32_t smem_u32(const void* p) {
    uint32_t a;
    asm("{ .reg .u64 t; cvta.to.shared.u64 t, %1; cvt.u32.u64 %0, t; }"
        : "=r"(a) : "l"(p));
    return a;
}
__device__ __forceinline__ void ldsm4(uint32_t* r, uint32_t addr) {
    asm volatile("ldmatrix.sync.aligned.m8n8.x4.shared.b16 {%0,%1,%2,%3}, [%4];"
        : "=r"(r[0]), "=r"(r[1]), "=r"(r[2]), "=r"(r[3]) : "r"(addr));
}
__device__ __forceinline__ void mma_bf16(float* d, const uint32_t* a,
                                         uint32_t b0, uint32_t b1) {
    asm volatile("mma.sync.aligned.m16n8k16.row.col.f32.bf16.bf16.f32 "
        "{%0,%1,%2,%3}, {%4,%5,%6,%7}, {%8,%9}, {%0,%1,%2,%3};"
        : "+f"(d[0]), "+f"(d[1]), "+f"(d[2]), "+f"(d[3])
        : "r"(a[0]), "r"(a[1]), "r"(a[2]), "r"(a[3]), "r"(b0), "r"(b1));
}
__device__ __forceinline__ void cpasync16(uint32_t dst, const void* src) {
    asm volatile("cp.async.cg.shared.global [%0], [%1], 16;"
                 :: "r"(dst), "l"(src));
}
#define CP_COMMIT() asm volatile("cp.async.commit_group;" ::: "memory")

// bulk DMA: gmem -> smem, completion via mbarrier complete_tx
__device__ __forceinline__ void bulkcp(uint32_t dst, const void* src,
                                       uint32_t bytes, uint32_t mbar) {
    asm volatile(
        "cp.async.bulk.shared::cluster.global.mbarrier::complete_tx::bytes "
        "[%0], [%1], %2, [%3];"
        :: "r"(dst), "l"(src), "r"(bytes), "r"(mbar) : "memory");
}
__device__ __forceinline__ void mbar_init(uint32_t mbar, uint32_t cnt) {
    asm volatile("mbarrier.init.shared.b64 [%0], %1;"
                 :: "r"(mbar), "r"(cnt) : "memory");
}
__device__ __forceinline__ void mbar_expect(uint32_t mbar, uint32_t bytes) {
    asm volatile("mbarrier.arrive.expect_tx.shared.b64 _, [%0], %1;"
                 :: "r"(mbar), "r"(bytes) : "memory");
}
__device__ __forceinline__ void mbar_wait(uint32_t mbar, uint32_t parity) {
    asm volatile("{\n\t.reg .pred P;\n\tWL%=:\n\t"
                 "mbarrier.try_wait.parity.acquire.cta.shared::cta.b64 P, [%0], %1;\n\t"
                 "@!P bra WL%=;\n\t}" :: "r"(mbar), "r"(parity) : "memory");
}

// ---------------------------------------------------------------------------
// Device scratch
// ---------------------------------------------------------------------------
__device__ float g_gx[MROWS * 1536];             // input projections (fp32)
__device__ float g_x3[MROWS * DD];               // FFN layer-3 output (fp32)
__device__ __nv_bfloat16 g_A0 [MROWS * 1024];    // x0 split planes (hi|lo)
__device__ __nv_bfloat16 g_e2 [MROWS * 1024];    // emotions split planes
__device__ __nv_bfloat16 g_x1b[MROWS * 1024];
__device__ __nv_bfloat16 g_x2b[MROWS * 1024];
__device__ __nv_bfloat16 g_Wih2[1536 * 1024];    // weight split planes
__device__ __nv_bfloat16 g_W12 [512 * 1024];
__device__ __nv_bfloat16 g_W22 [512 * 1024];
__device__ __nv_bfloat16 g_W32 [512 * 1024];
// GRU h planes, padded layout for bulk DMA:
// [2 bufs][4 groups][2 planes][32 batches][520]  (row = plane*32+batch)
#define HROW 520
#define HGRP (2 * 32 * HROW)                     // 33280 elems / 66560 B
__device__ __nv_bfloat16 g_h2[2 * 4 * HGRP];
__device__ float g_Wc[NCLS * DD];
__device__ float g_s [NCLS];
__device__ float g_bc[NCLS];
__device__ unsigned g_ctr4[4 * 32];              // barrier counters, 128B apart

// ---------------------------------------------------------------------------
// Init: zero h planes buffer 0 + barrier counters (reset every graph replay)
// ---------------------------------------------------------------------------
__global__ void k_init() {
    int idx = blockIdx.x * 256 + threadIdx.x;   // 520 blocks = 133120 threads
    if (idx < 4 * HGRP / 2) {
        ((__nv_bfloat162*)g_h2)[idx] = __nv_bfloat162{__nv_bfloat16(0.f),
                                                      __nv_bfloat16(0.f)};
    }
    if (idx < 4) g_ctr4[idx * 32] = 0u;
}

// ---------------------------------------------------------------------------
// prep1/prep2: fold log_softmax + classifier head
// ---------------------------------------------------------------------------
__global__ void k_prep1(const float* __restrict__ W_half,
                        const float* __restrict__ W_out) {
    int idx = blockIdx.x * 256 + threadIdx.x;
    if (idx >= NCLS * DD) return;
    int n = idx / DD, k = idx % DD;
    float s = 0.0f;
    for (int j = 0; j < 256; j++)
        s += W_out[n * 256 + j] * W_half[j * DD + k];
    g_Wc[idx] = s;
}
__global__ void k_prep2(const float* __restrict__ W_out,
                        const float* __restrict__ b_half,
                        const float* __restrict__ b_out) {
    int tid = threadIdx.x;
    int w = tid >> 5, l = tid & 31;
    if (w < NCLS) {
        float s = 0.0f;
        #pragma unroll
        for (int i = 0; i < 16; i++) s += g_Wc[w * DD + i * 32 + l];
        #pragma unroll
        for (int off = 16; off > 0; off >>= 1)
            s += __shfl_xor_sync(0xffffffffu, s, off);
        if (l == 0) g_s[w] = s;
    }
    if (tid < NCLS) {
        float b = b_out[tid];
        for (int j = 0; j < 256; j++)
            b += W_out[tid * 256 + j] * b_half[j];
        g_bc[tid] = b;
    }
}

// ---------------------------------------------------------------------------
// k_split: fp32 [rows,512] -> bf16 hi/lo planes [rows,1024]
// ---------------------------------------------------------------------------
__global__ void k_split(const float* __restrict__ src,
                        __nv_bfloat16* __restrict__ dst,
                        int nrows, int perm) {
    int idx = blockIdx.x * 256 + threadIdx.x;
    if (idx >= nrows * 128) return;
    int r = idx >> 7, c4 = (idx & 127) << 2;
    size_t so = perm ? ((size_t)((r >> 8) * 512 + (r & 255)) * 512)
                     : ((size_t)r * 512);
    float4 v = *(const float4*)(src + so + c4);
    __nv_bfloat16 h[4], lo[4];
    float vv[4] = {v.x, v.y, v.z, v.w};
    #pragma unroll
    for (int i = 0; i < 4; i++) {
        h[i] = __float2bfloat16(vv[i]);
        lo[i] = __float2bfloat16(vv[i] - __bfloat162float(h[i]));
    }
    *(ull*)(dst + (size_t)r * 1024 + c4)       = *(ull*)h;
    *(ull*)(dst + (size_t)r * 1024 + 512 + c4) = *(ull*)lo;
}

// ---------------------------------------------------------------------------
// mma.sync bf16-split GEMM, 128x128 tile, BK=64 (24 chunks), 3-stage pipeline.
//   C[m,n] = act( sum_k A[m,k]*B[n,k] + bias[n] ),  K' = 1536 (3 segments).
// ---------------------------------------------------------------------------
#define ROWB 144         // padded smem row: 64 bf16 (128B) + 16B pad
#define BUFB (128 * ROWB)    // 18432
#define NST  3
#define GEMM_SMEM (2 * NST * BUFB)   // 110592

__global__ void __launch_bounds__(256, 2)
k_mma_gemm(const __nv_bfloat16* __restrict__ A,
           const __nv_bfloat16* __restrict__ Bw,
           const float* __restrict__ bias,
           void* __restrict__ Cout,
           int Ntot, int n_tiles, int mode) {
    extern __shared__ __align__(16) char smc[];
    uint32_t sbase = smem_u32(smc);
    int tid = threadIdx.x, wid = tid >> 5, lane = tid & 31;
    int m0 = (blockIdx.x / n_tiles) << 7;
    int n0 = (blockIdx.x % n_tiles) << 7;

    int sr2 = tid >> 3;          // staging row (0..31), +32/+64/+96
    int sc2 = tid & 7;           // 16B column chunk (0..7 => 128B row)

    float acc[2][8][4];
    #pragma unroll
    for (int i = 0; i < 2; i++)
        #pragma unroll
        for (int j = 0; j < 8; j++)
            #pragma unroll
            for (int q = 0; q < 4; q++) acc[i][j][q] = 0.0f;

    auto issue = [&](int c) {
        int seg = c >> 3, kofs = (c & 7) << 6;
        int asel = (seg == 1) ? 512 : 0;
        int bsel = (seg == 2) ? 512 : 0;
        const __nv_bfloat16* Ag = A + (size_t)m0 * 1024 + asel + kofs;
        const __nv_bfloat16* Bg = Bw + (size_t)n0 * 1024 + bsel + kofs;
        int buf = c % NST;
        uint32_t da = sbase + (uint32_t)buf * BUFB;
        uint32_t db = sbase + (uint32_t)(NST + buf) * BUFB;
        #pragma unroll
        for (int rr = 0; rr < 4; rr++) {
            int row = sr2 + rr * 32;
            cpasync16(da + row * ROWB + sc2 * 16, Ag + (size_t)row * 1024 + sc2 * 8);
            cpasync16(db + row * ROWB + sc2 * 16, Bg + (size_t)row * 1024 + sc2 * 8);
        }
        CP_COMMIT();
    };

    issue(0);
    issue(1);

    int wm = wid & 3;
    int wn = wid >> 2;
    uint32_t a_row  = (uint32_t)(wm * 32 + (lane & 15));
    uint32_t a_colb = (uint32_t)((lane >> 4) * 16);
    uint32_t b_row  = (uint32_t)(wn * 64 + (lane & 7));
    uint32_t b_colb = (uint32_t)((lane >> 3) * 16);

    for (int c = 0; c < 24; c++) {
        if (c < 23) asm volatile("cp.async.wait_group 1;" ::: "memory");
        else        asm volatile("cp.async.wait_group 0;" ::: "memory");
        __syncthreads();
        if (c + 2 < 24) issue(c + 2);

        int buf = c % NST;
        uint32_t sA = sbase + (uint32_t)buf * BUFB;
        uint32_t sB = sbase + (uint32_t)(NST + buf) * BUFB;

        #pragma unroll
        for (int kh = 0; kh < 2; kh++) {
            uint32_t bf[8][4];
            #pragma unroll
            for (int nt = 0; nt < 8; nt++)
                ldsm4(bf[nt], sB + (b_row + nt * 8) * ROWB + kh * 64 + b_colb);

            #pragma unroll
            for (int ks = 0; ks < 2; ks++) {
                uint32_t af[2][4];
                ldsm4(af[0], sA + a_row * ROWB + kh * 64 + ks * 32 + a_colb);
                ldsm4(af[1], sA + (a_row + 16) * ROWB + kh * 64 + ks * 32 + a_colb);
                #pragma unroll
                for (int mi = 0; mi < 2; mi++)
                    #pragma unroll
                    for (int nt = 0; nt < 8; nt++)
                        mma_bf16(acc[mi][nt], af[mi], bf[nt][2 * ks], bf[nt][2 * ks + 1]);
            }
        }
    }

    int gid = lane >> 2, tig = lane & 3;
    float bv[16];
    #pragma unroll
    for (int nt = 0; nt < 8; nt++) {
        int col = n0 + wn * 64 + nt * 8 + 2 * tig;
        bv[nt * 2]     = bias[col];
        bv[nt * 2 + 1] = bias[col + 1];
    }
    #pragma unroll
    for (int mi = 0; mi < 2; mi++) {
        int mrow = m0 + wm * 32 + mi * 16 + gid;
        #pragma unroll
        for (int nt = 0; nt < 8; nt++) {
            int col = n0 + wn * 64 + nt * 8 + 2 * tig;
            float v0 = acc[mi][nt][0] + bv[nt * 2];
            float v1 = acc[mi][nt][1] + bv[nt * 2 + 1];
            float v2 = acc[mi][nt][2] + bv[nt * 2];
            float v3 = acc[mi][nt][3] + bv[nt * 2 + 1];
            if (mode == 0) {
                float* C = (float*)Cout;
                float2 p0 = {v0, v1}, p1 = {v2, v3};
                *(float2*)&C[(size_t)mrow * Ntot + col]       = p0;
                *(float2*)&C[(size_t)(mrow + 8) * Ntot + col] = p1;
            } else {
                __nv_bfloat16* C = (__nv_bfloat16*)Cout;
                v0 = tanhf(v0); v1 = tanhf(v1); v2 = tanhf(v2); v3 = tanhf(v3);
                __nv_bfloat16 h0 = __float2bfloat16(v0), h1 = __float2bfloat16(v1);
                __nv_bfloat16 h2 = __float2bfloat16(v2), h3 = __float2bfloat16(v3);
                __nv_bfloat16 l0 = __float2bfloat16(v0 - __bfloat162float(h0));
                __nv_bfloat16 l1 = __float2bfloat16(v1 - __bfloat162float(h1));
                __nv_bfloat16 l2 = __float2bfloat16(v2 - __bfloat162float(h2));
                __nv_bfloat16 l3 = __float2bfloat16(v3 - __bfloat162float(h3));
                __nv_bfloat162 ph0 = {h0, h1}, ph1 = {h2, h3};
                __nv_bfloat162 pl0 = {l0, l1}, pl1 = {l2, l3};
                *(__nv_bfloat162*)&C[(size_t)mrow * 1024 + col]             = ph0;
                *(__nv_bfloat162*)&C[(size_t)mrow * 1024 + 512 + col]       = pl0;
                *(__nv_bfloat162*)&C[(size_t)(mrow + 8) * 1024 + col]       = ph1;
                *(__nv_bfloat162*)&C[(size_t)(mrow + 8) * 1024 + 512 + col] = pl1;
            }
        }
    }
}

// ---------------------------------------------------------------------------
// Persistent GRU scan (R13 proven: W-hi regs + bulk-DMA) with e2 stores
// moved after the barrier arrive (off the fenced critical path).
// ---------------------------------------------------------------------------
#define SC_STRIDE 520                            // bf16 elems/row -> 1040 B
#define SC_W_BYTES (96 * SC_STRIDE * 2)          // 99840
#define SC_H_BYTES (64 * SC_STRIDE * 2)          // 66560
#define SC_GH_F    (48 * 33)
#define SCAN_SMEM_BYTES (SC_W_BYTES + SC_H_BYTES + SC_GH_F * 4 + 256)

__global__ void __launch_bounds__(256, 1)
k_scan(const float* __restrict__ Whh, const float* __restrict__ bhh) {
    extern __shared__ __align__(16) char dynsm[];
    __nv_bfloat16* ws  = (__nv_bfloat16*)dynsm;
    __nv_bfloat16* hsb = (__nv_bfloat16*)(dynsm + SC_W_BYTES);
    float* gh  = (float*)(dynsm + SC_W_BYTES + SC_H_BYTES);
    float* bsh = gh + SC_GH_F;
    uint32_t ws_u = smem_u32(ws);
    uint32_t hs_u = smem_u32(hsb);
    uint32_t mbA = smem_u32(dynsm + SC_W_BYTES + SC_H_BYTES + SC_GH_F * 4 + 192);
    uint32_t mbB = mbA + 8;

    int tid = threadIdx.x, wid = tid >> 5, lane = tid & 31;
    int blk = blockIdx.x;
    int bg = blk >> 5, dg = blk & 31;
    int d0 = dg << 4, b0 = bg << 5;

    // Load W slice once, split into bf16 hi/lo plane rows.
    for (int i = tid; i < 48 * 512; i += 256) {
        int j = i >> 9, k = i & 511;            // j = gate*16 + dc
        int g = j >> 4, dc = j & 15;
        float w = Whh[(size_t)(g * 512 + d0 + dc) * 512 + k];
        __nv_bfloat16 hi = __float2bfloat16(w);
        __nv_bfloat16 lo = __float2bfloat16(w - __bfloat162float(hi));
        ws[j * SC_STRIDE + k]        = hi;
        ws[(48 + j) * SC_STRIDE + k] = lo;
    }
    if (tid < 48) bsh[tid] = bhh[(tid >> 4) * 512 + d0 + (tid & 15)];
    if (tid == 0) { mbar_init(mbA, 1); mbar_init(mbB, 1); }
    __syncthreads();

    int mt = wid % 3, nh = wid / 3;             // mma mapping (wid < 6)
    uint32_t aw_hi = ws_u + (uint32_t)((mt * 16 + (lane & 15)) * 1040)
                   + ((lane >> 4) << 4);
    uint32_t aw_lo = aw_hi + 48u * 1040u;
    uint32_t bh_hi = hs_u + (uint32_t)((nh * 16 + (lane & 7)) * 1040)
                   + ((lane >> 3) << 4);
    uint32_t bh_lo = bh_hi + 32u * 1040u;

    // Hoist W-hi fragments into registers (loop-invariant across 256 steps).
    uint32_t ahr[16][2][4];
    if (wid < 6) {
        #pragma unroll
        for (int k32 = 0; k32 < 16; k32++) {
            ldsm4(ahr[k32][0], aw_hi + (k32 << 6));
            ldsm4(ahr[k32][1], aw_hi + (k32 << 6) + 32);
        }
    }

    int bi_a = tid >> 4;                        // epilogue: batches bi_a, +16
    int dc_a = tid & 15;
    int d_a = d0 + dc_a;
    int p = 0;

    for (int t = 0; t < HALF_T; t++) {
        // prefetch gx gate values (overlaps DMA)
        size_t rowA = ((size_t)(b0 + bi_a) * 256 + t) * 1536;
        size_t rowB = ((size_t)(b0 + bi_a + 16) * 256 + t) * 1536;
        float gxrA = __ldcg(g_gx + rowA + d_a);
        float gxzA = __ldcg(g_gx + rowA + 512 + d_a);
        float gxnA = __ldcg(g_gx + rowA + 1024 + d_a);
        float gxrB = __ldcg(g_gx + rowB + d_a);
        float gxzB = __ldcg(g_gx + rowB + 512 + d_a);
        float gxnB = __ldcg(g_gx + rowB + 1024 + d_a);

        // bulk-DMA stage h planes (hi block then lo block)
        if (tid == 0) {
            const __nv_bfloat16* src = g_h2 + ((size_t)p * 4 + bg) * HGRP;
            mbar_expect(mbA, 33280u);
            mbar_expect(mbB, 33280u);
            bulkcp(hs_u,          src,         33280u, mbA);
            bulkcp(hs_u + 33280u, src + 16640, 33280u, mbB);
        }
        mbar_wait(mbA, (uint32_t)(t & 1));      // hi plane visible

        // hi phase: (Whi + Wlo) x h_hi, lo DMA still in flight
        float acc[2][4];
        if (wid < 6) {
            #pragma unroll
            for (int nt = 0; nt < 2; nt++)
                #pragma unroll
                for (int q = 0; q < 4; q++) acc[nt][q] = 0.0f;
            #pragma unroll
            for (int k32 = 0; k32 < 16; k32++) {
                int kb = k32 << 6;
                uint32_t al0[4], al1[4], bf0[4], bf1[4];
                ldsm4(al0, aw_lo + kb);
                ldsm4(al1, aw_lo + kb + 32);
                ldsm4(bf0, bh_hi + kb);
                ldsm4(bf1, bh_hi + kb + 8 * 1040);
                mma_bf16(acc[0], ahr[k32][0], bf0[0], bf0[1]);
                mma_bf16(acc[1], ahr[k32][0], bf1[0], bf1[1]);
                mma_bf16(acc[0], ahr[k32][1], bf0[2], bf0[3]);
                mma_bf16(acc[1], ahr[k32][1], bf1[2], bf1[3]);
                mma_bf16(acc[0], al0, bf0[0], bf0[1]);
                mma_bf16(acc[1], al0, bf1[0], bf1[1]);
                mma_bf16(acc[0], al1, bf0[2], bf0[3]);
                mma_bf16(acc[1], al1, bf1[2], bf1[3]);
            }
        }
        mbar_wait(mbB, (uint32_t)(t & 1));      // lo plane visible

        if (wid < 6) {
            #pragma unroll
            for (int k32 = 0; k32 < 16; k32++) {
                int kb = k32 << 6;
                uint32_t bl0[4], bl1[4];
                ldsm4(bl0, bh_lo + kb);
                ldsm4(bl1, bh_lo + kb + 8 * 1040);
                mma_bf16(acc[0], ahr[k32][0], bl0[0], bl0[1]);
                mma_bf16(acc[1], ahr[k32][0], bl1[0], bl1[1]);
                mma_bf16(acc[0], ahr[k32][1], bl0[2], bl0[3]);
                mma_bf16(acc[1], ahr[k32][1], bl1[2], bl1[3]);
            }
            // write gh fragments
            int r = lane >> 2, c = (lane & 3) << 1;
            #pragma unroll
            for (int nt = 0; nt < 2; nt++) {
                int n = nh * 16 + nt * 8 + c;
                int m = mt * 16 + r;
                gh[m * 33 + n]           = acc[nt][0];
                gh[m * 33 + n + 1]       = acc[nt][1];
                gh[(m + 8) * 33 + n]     = acc[nt][2];
                gh[(m + 8) * 33 + n + 1] = acc[nt][3];
            }
        }
        __syncthreads();

        // epilogue: 2 outputs per thread; h stores on the fenced path,
        // e2 stores deferred past the barrier arrive.
        __nv_bfloat16 ehi[2], elo[2];
        #pragma unroll
        for (int half = 0; half < 2; half++) {
            int bi = bi_a + (half << 4);
            float gxr = half ? gxrB : gxrA;
            float gxz = half ? gxzB : gxzA;
            float gxn = half ? gxnB : gxnA;
            float ghr = gh[dc_a * 33 + bi]        + bsh[dc_a];
            float ghz = gh[(16 + dc_a) * 33 + bi] + bsh[16 + dc_a];
            float ghn = gh[(32 + dc_a) * 33 + bi] + bsh[32 + dc_a];
            float r = 1.0f / (1.0f + __expf(-(gxr + ghr)));
            float z = 1.0f / (1.0f + __expf(-(gxz + ghz)));
            float n = tanhf(gxn + r * ghn);
            float hold = __bfloat162float(hsb[bi * SC_STRIDE + d_a])
                       + __bfloat162float(hsb[(32 + bi) * SC_STRIDE + d_a]);
            float hn = (1.0f - z) * n + z * hold;
            __nv_bfloat16 hi = __float2bfloat16(hn);
            __nv_bfloat16 lo = __float2bfloat16(hn - __bfloat162float(hi));
            ehi[half] = hi; elo[half] = lo;
            if (t < HALF_T - 1) {
                size_t gb = ((size_t)(p ^ 1) * 4 + bg) * HGRP;
                g_h2[gb + bi * HROW + d_a]         = hi;
                g_h2[gb + 16640 + bi * HROW + d_a] = lo;
            }
        }

        if (t < HALF_T - 1) {
            __threadfence();                    // drain h stores
            __syncthreads();
            if (tid == 0) atomicAdd(&g_ctr4[bg * 32], 1u);   // arrive
        }

        // e2 stores overlap the peer wait
        #pragma unroll
        for (int half = 0; half < 2; half++) {
            int bi = bi_a + (half << 4);
            size_t erow = ((size_t)(b0 + bi) * 256 + t) * 1024;
            g_e2[erow + d_a]       = ehi[half];
            g_e2[erow + 512 + d_a] = elo[half];
        }

        if (t < HALF_T - 1) {
            if (tid == 0) {
                unsigned target = (unsigned)(t + 1) * 32u;
                volatile unsigned* vc = &g_ctr4[bg * 32];
                while (*vc < target) { }
            }
            __syncthreads();
        }
        p ^= 1;
    }
}

// ---------------------------------------------------------------------------
// Fused head: out[m] = logsoftmax(f[m]) @ W_comb^T + b_comb
// ---------------------------------------------------------------------------
__global__ void __launch_bounds__(256)
k_final(const float* __restrict__ X, float* __restrict__ out) {
    __shared__ float Wc[NCLS * DD];
    __shared__ float ss[NCLS], bc[NCLS];
    int tid = threadIdx.x;
    for (int idx = tid; idx < NCLS * DD; idx += 256) Wc[idx] = g_Wc[idx];
    if (tid < NCLS) { ss[tid] = g_s[tid]; bc[tid] = g_bc[tid]; }
    __syncthreads();

    int w = tid >> 5, l = tid & 31;
    int m = (blockIdx.x << 3) + w;
    const float* xr = X + (size_t)m * DD;

    float f[16];
    #pragma unroll
    for (int i = 0; i < 16; i++) f[i] = xr[i * 32 + l];

    float mx = f[0];
    #pragma unroll
    for (int i = 1; i < 16; i++) mx = fmaxf(mx, f[i]);
    #pragma unroll
    for (int off = 16; off > 0; off >>= 1)
        mx = fmaxf(mx, __shfl_xor_sync(0xffffffffu, mx, off));

    float se = 0.0f;
    #pragma unroll
    for (int i = 0; i < 16; i++) se += __expf(f[i] - mx);
    #pragma unroll
    for (int off = 16; off > 0; off >>= 1)
        se += __shfl_xor_sync(0xffffffffu, se, off);
    float c = mx + __logf(se);

    #pragma unroll
    for (int n = 0; n < NCLS; n++) {
        float dot = 0.0f;
        const float* wr = Wc + n * DD;
        #pragma unroll
        for (int i = 0; i < 16; i++) dot += f[i] * wr[i * 32 + l];
        #pragma unroll
        for (int off = 16; off > 0; off >>= 1)
            dot += __shfl_xor_sync(0xffffffffu, dot, off);
        if (l == 0) out[m * NCLS + n] = dot - c * ss[n] + bc[n];
    }
}

// ---------------------------------------------------------------------------
// kernel_launch — ordered so k_scan is launch index 5 (ncu -s 5 -c 1 target)
// ---------------------------------------------------------------------------
extern "C" void kernel_launch(void* const* d_in, const int* in_sizes, int n_in,
                              void* d_out, int out_size) {
    (void)in_sizes; (void)out_size;
    if (n_in < 17) return;
    const float* x0     = (const float*)d_in[0];
    const float* W_ih   = (const float*)d_in[3];
    const float* W_hh   = (const float*)d_in[4];
    const float* b_ih   = (const float*)d_in[5];
    const float* b_hh   = (const float*)d_in[6];
    const float* W1     = (const float*)d_in[7];
    const float* bb1    = (const float*)d_in[8];
    const float* W2     = (const float*)d_in[9];
    const float* bb2    = (const float*)d_in[10];
    const float* W3     = (const float*)d_in[11];
    const float* bb3    = (const float*)d_in[12];
    const float* W_half = (const float*)d_in[13];
    const float* b_half = (const float*)d_in[14];
    const float* W_out  = (const float*)d_in[15];
    const float* b_out  = (const float*)d_in[16];
    float* out = (float*)d_out;

    float *gx, *x3;
    __nv_bfloat16 *A0, *e2, *x1b, *x2b, *Wih2, *W12, *W22, *W32;
    cudaGetSymbolAddress((void**)&gx,   g_gx);
    cudaGetSymbolAddress((void**)&x3,   g_x3);
    cudaGetSymbolAddress((void**)&A0,   g_A0);
    cudaGetSymbolAddress((void**)&e2,   g_e2);
    cudaGetSymbolAddress((void**)&x1b,  g_x1b);
    cudaGetSymbolAddress((void**)&x2b,  g_x2b);
    cudaGetSymbolAddress((void**)&Wih2, g_Wih2);
    cudaGetSymbolAddress((void**)&W12,  g_W12);
    cudaGetSymbolAddress((void**)&W22,  g_W22);
    cudaGetSymbolAddress((void**)&W32,  g_W32);

    cudaFuncSetAttribute(k_scan, cudaFuncAttributeMaxDynamicSharedMemorySize,
                         SCAN_SMEM_BYTES);
    cudaFuncSetAttribute(k_mma_gemm, cudaFuncAttributeMaxDynamicSharedMemorySize,
                         GEMM_SMEM);

    // 0,1: input/weight splits needed by gx GEMM
    k_split<<<(MROWS * 128) / 256, 256>>>(x0, A0, MROWS, 1);
    k_split<<<(1536 * 128) / 256, 256>>>(W_ih, Wih2, 1536, 0);
    // 2: init h planes + barrier counters
    k_init<<<520, 256>>>();
    // 3: gx = x0 @ W_ih^T + b_ih   [32768 x 1536]  (128x128 tiles, BK=64)
    k_mma_gemm<<<256 * 12, 256, GEMM_SMEM>>>(A0, Wih2, b_ih, gx, 1536, 12, 0);
    // 4: head fold (independent)
    k_prep1<<<14, 256>>>(W_half, W_out);
    // 5: GRU scan (PROFILED)
    k_scan<<<128, 256, SCAN_SMEM_BYTES>>>(W_hh, b_hh);
    // 6: head fold part 2
    k_prep2<<<1, 256>>>(W_out, b_half, b_out);
    // 7-9: FFN weight splits
    k_split<<<(512 * 128) / 256, 256>>>(W1, W12, 512, 0);
    k_split<<<(512 * 128) / 256, 256>>>(W2, W22, 512, 0);
    k_split<<<(512 * 128) / 256, 256>>>(W3, W32, 512, 0);
    // 10-12: FFN (128x128 tiles, BK=64)
    k_mma_gemm<<<256 * 4, 256, GEMM_SMEM>>>(e2,  W12, bb1, x1b, 512, 4, 1);
    k_mma_gemm<<<256 * 4, 256, GEMM_SMEM>>>(x1b, W22, bb2, x2b, 512, 4, 1);
    k_mma_gemm<<<256 * 4, 256, GEMM_SMEM>>>(x2b, W32, bb3, x3,  512, 4, 0);
    // 13: fused log_softmax + combined classifier head
    k_final<<<MROWS / 8, 256>>>(x3, out);
}

// round 15
// speedup vs baseline: 1.2842x; 1.0082x over previous
#include <cuda_runtime.h>
#include <cuda_bf16.h>
#include <cstddef>
#include <cstdint>

// Problem constants
#define BB     128
#define TT     512
#define HALF_T 256
#define DD     512
#define NCLS   7
#define MROWS  (BB * HALF_T)   // 32768 rows fed to FFN / head

typedef unsigned long long ull;

// ---------------------------------------------------------------------------
// mma.sync / ldmatrix / cp.async / bulk-DMA helpers (baseline PTX, sm_100-safe)
// ---------------------------------------------------------------------------
__device__ __forceinline__ uint32_t smem_u32(const void* p) {
    uint32_t a;
    asm("{ .reg .u64 t; cvta.to.shared.u64 t, %1; cvt.u32.u64 %0, t; }"
        : "=r"(a) : "l"(p));
    return a;
}
__device__ __forceinline__ void ldsm4(uint32_t* r, uint32_t addr) {
    asm volatile("ldmatrix.sync.aligned.m8n8.x4.shared.b16 {%0,%1,%2,%3}, [%4];"
        : "=r"(r[0]), "=r"(r[1]), "=r"(r[2]), "=r"(r[3]) : "r"(addr));
}
__device__ __forceinline__ void mma_bf16(float* d, const uint32_t* a,
                                         uint32_t b0, uint32_t b1) {
    asm volatile("mma.sync.aligned.m16n8k16.row.col.f32.bf16.bf16.f32 "
        "{%0,%1,%2,%3}, {%4,%5,%6,%7}, {%8,%9}, {%0,%1,%2,%3};"
        : "+f"(d[0]), "+f"(d[1]), "+f"(d[2]), "+f"(d[3])
        : "r"(a[0]), "r"(a[1]), "r"(a[2]), "r"(a[3]), "r"(b0), "r"(b1));
}
__device__ __forceinline__ void cpasync16(uint32_t dst, const void* src) {
    asm volatile("cp.async.cg.shared.global [%0], [%1], 16;"
                 :: "r"(dst), "l"(src));
}
#define CP_COMMIT() asm volatile("cp.async.commit_group;" ::: "memory")

// bulk DMA: gmem -> smem, completion via mbarrier complete_tx
__device__ __forceinline__ void bulkcp(uint32_t dst, const void* src,
                                       uint32_t bytes, uint32_t mbar) {
    asm volatile(
        "cp.async.bulk.shared::cluster.global.mbarrier::complete_tx::bytes "
        "[%0], [%1], %2, [%3];"
        :: "r"(dst), "l"(src), "r"(bytes), "r"(mbar) : "memory");
}
__device__ __forceinline__ void mbar_init(uint32_t mbar, uint32_t cnt) {
    asm volatile("mbarrier.init.shared.b64 [%0], %1;"
                 :: "r"(mbar), "r"(cnt) : "memory");
}
__device__ __forceinline__ void mbar_expect(uint32_t mbar, uint32_t bytes) {
    asm volatile("mbarrier.arrive.expect_tx.shared.b64 _, [%0], %1;"
                 :: "r"(mbar), "r"(bytes) : "memory");
}
__device__ __forceinline__ void mbar_wait(uint32_t mbar, uint32_t parity) {
    asm volatile("{\n\t.reg .pred P;\n\tWL%=:\n\t"
                 "mbarrier.try_wait.parity.acquire.cta.shared::cta.b64 P, [%0], %1;\n\t"
                 "@!P bra WL%=;\n\t}" :: "r"(mbar), "r"(parity) : "memory");
}
__device__ __forceinline__ void arrive_release(unsigned* ctr) {
    unsigned old;
    asm volatile("atom.release.gpu.global.add.u32 %0, [%1], 1;"
                 : "=r"(old) : "l"(ctr) : "memory");
}
__device__ __forceinline__ unsigned ld_acquire(const unsigned* ctr) {
    unsigned v;
    asm volatile("ld.acquire.gpu.global.u32 %0, [%1];"
                 : "=r"(v) : "l"(ctr) : "memory");
    return v;
}

// ---------------------------------------------------------------------------
// Device scratch
// ---------------------------------------------------------------------------
__device__ float g_gx[MROWS * 1536];             // input projections (fp32)
__device__ float g_x3[MROWS * DD];               // FFN layer-3 output (fp32)
__device__ __nv_bfloat16 g_A0 [MROWS * 1024];    // x0 split planes (hi|lo)
__device__ __nv_bfloat16 g_e2 [MROWS * 1024];    // emotions split planes
__device__ __nv_bfloat16 g_x1b[MROWS * 1024];
__device__ __nv_bfloat16 g_x2b[MROWS * 1024];
__device__ __nv_bfloat16 g_Wih2[1536 * 1024];    // weight split planes
__device__ __nv_bfloat16 g_W12 [512 * 1024];
__device__ __nv_bfloat16 g_W22 [512 * 1024];
__device__ __nv_bfloat16 g_W32 [512 * 1024];
// GRU h planes, padded layout for bulk DMA:
// [2 bufs][4 groups][2 planes][32 batches][520]  (row = plane*32+batch)
#define HROW 520
#define HGRP (2 * 32 * HROW)                     // 33280 elems / 66560 B
__device__ __nv_bfloat16 g_h2[2 * 4 * HGRP];
__device__ float g_Wc[NCLS * DD];
__device__ float g_s [NCLS];
__device__ float g_bc[NCLS];
__device__ unsigned g_ctr4[4 * 32];              // barrier counters, 128B apart

// ---------------------------------------------------------------------------
// Init: zero h planes buffer 0 + barrier counters (reset every graph replay)
// ---------------------------------------------------------------------------
__global__ void k_init() {
    int idx = blockIdx.x * 256 + threadIdx.x;   // 520 blocks = 133120 threads
    if (idx < 4 * HGRP / 2) {
        ((__nv_bfloat162*)g_h2)[idx] = __nv_bfloat162{__nv_bfloat16(0.f),
                                                      __nv_bfloat16(0.f)};
    }
    if (idx < 4) g_ctr4[idx * 32] = 0u;
}

// ---------------------------------------------------------------------------
// prep1/prep2: fold log_softmax + classifier head
// ---------------------------------------------------------------------------
__global__ void k_prep1(const float* __restrict__ W_half,
                        const float* __restrict__ W_out) {
    int idx = blockIdx.x * 256 + threadIdx.x;
    if (idx >= NCLS * DD) return;
    int n = idx / DD, k = idx % DD;
    float s = 0.0f;
    for (int j = 0; j < 256; j++)
        s += W_out[n * 256 + j] * W_half[j * DD + k];
    g_Wc[idx] = s;
}
__global__ void k_prep2(const float* __restrict__ W_out,
                        const float* __restrict__ b_half,
                        const float* __restrict__ b_out) {
    int tid = threadIdx.x;
    int w = tid >> 5, l = tid & 31;
    if (w < NCLS) {
        float s = 0.0f;
        #pragma unroll
        for (int i = 0; i < 16; i++) s += g_Wc[w * DD + i * 32 + l];
        #pragma unroll
        for (int off = 16; off > 0; off >>= 1)
            s += __shfl_xor_sync(0xffffffffu, s, off);
        if (l == 0) g_s[w] = s;
    }
    if (tid < NCLS) {
        float b = b_out[tid];
        for (int j = 0; j < 256; j++)
            b += W_out[tid * 256 + j] * b_half[j];
        g_bc[tid] = b;
    }
}

// ---------------------------------------------------------------------------
// k_split: fp32 [rows,512] -> bf16 hi/lo planes [rows,1024]
// ---------------------------------------------------------------------------
__device__ __forceinline__ void split_row(const float* src, __nv_bfloat16* dst,
                                          size_t so, size_t dro, int c4) {
    float4 v = *(const float4*)(src + so + c4);
    __nv_bfloat16 h[4], lo[4];
    float vv[4] = {v.x, v.y, v.z, v.w};
    #pragma unroll
    for (int i = 0; i < 4; i++) {
        h[i] = __float2bfloat16(vv[i]);
        lo[i] = __float2bfloat16(vv[i] - __bfloat162float(h[i]));
    }
    *(ull*)(dst + dro + c4)       = *(ull*)h;
    *(ull*)(dst + dro + 512 + c4) = *(ull*)lo;
}

__global__ void k_split(const float* __restrict__ src,
                        __nv_bfloat16* __restrict__ dst,
                        int nrows, int perm) {
    int idx = blockIdx.x * 256 + threadIdx.x;
    if (idx >= nrows * 128) return;
    int r = idx >> 7, c4 = (idx & 127) << 2;
    size_t so = perm ? ((size_t)((r >> 8) * 512 + (r & 255)) * 512)
                     : ((size_t)r * 512);
    split_row(src, dst, so, (size_t)r * 1024, c4);
}

// merged FFN weight split: W1/W2/W3 -> g_W12/g_W22/g_W32 in ONE launch
__global__ void k_splitW(const float* __restrict__ W1,
                         const float* __restrict__ W2,
                         const float* __restrict__ W3) {
    int idx = blockIdx.x * 256 + threadIdx.x;   // 768 blocks = 196608
    int which = idx / (512 * 128);
    int rem = idx - which * (512 * 128);
    int r = rem >> 7, c4 = (rem & 127) << 2;
    const float* src = (which == 0) ? W1 : (which == 1) ? W2 : W3;
    __nv_bfloat16* dst = (which == 0) ? g_W12 : (which == 1) ? g_W22 : g_W32;
    split_row(src, dst, (size_t)r * 512, (size_t)r * 1024, c4);
}

// ---------------------------------------------------------------------------
// mma.sync bf16-split GEMM, 128x128 tile, BK=64 (24 chunks), 3-stage pipeline
// (exact R14 config — proven 495 us on gx).
// ---------------------------------------------------------------------------
#define ROWB 144         // padded smem row: 64 bf16 (128B) + 16B pad
#define BUFB (128 * ROWB)    // 18432
#define NST  3
#define GEMM_SMEM (2 * NST * BUFB)   // 110592

__global__ void __launch_bounds__(256, 2)
k_mma_gemm(const __nv_bfloat16* __restrict__ A,
           const __nv_bfloat16* __restrict__ Bw,
           const float* __restrict__ bias,
           void* __restrict__ Cout,
           int Ntot, int n_tiles, int mode) {
    extern __shared__ __align__(16) char smc[];
    uint32_t sbase = smem_u32(smc);
    int tid = threadIdx.x, wid = tid >> 5, lane = tid & 31;
    int m0 = (blockIdx.x / n_tiles) << 7;
    int n0 = (blockIdx.x % n_tiles) << 7;

    int sr2 = tid >> 3;          // staging row (0..31), +32/+64/+96
    int sc2 = tid & 7;           // 16B column chunk (0..7 => 128B row)

    float acc[2][8][4];
    #pragma unroll
    for (int i = 0; i < 2; i++)
        #pragma unroll
        for (int j = 0; j < 8; j++)
            #pragma unroll
            for (int q = 0; q < 4; q++) acc[i][j][q] = 0.0f;

    auto issue = [&](int c) {
        int seg = c >> 3, kofs = (c & 7) << 6;
        int asel = (seg == 1) ? 512 : 0;
        int bsel = (seg == 2) ? 512 : 0;
        const __nv_bfloat16* Ag = A + (size_t)m0 * 1024 + asel + kofs;
        const __nv_bfloat16* Bg = Bw + (size_t)n0 * 1024 + bsel + kofs;
        int buf = c % NST;
        uint32_t da = sbase + (uint32_t)buf * BUFB;
        uint32_t db = sbase + (uint32_t)(NST + buf) * BUFB;
        #pragma unroll
        for (int rr = 0; rr < 4; rr++) {
            int row = sr2 + rr * 32;
            cpasync16(da + row * ROWB + sc2 * 16, Ag + (size_t)row * 1024 + sc2 * 8);
            cpasync16(db + row * ROWB + sc2 * 16, Bg + (size_t)row * 1024 + sc2 * 8);
        }
        CP_COMMIT();
    };

    issue(0);
    issue(1);

    int wm = wid & 3;
    int wn = wid >> 2;
    uint32_t a_row  = (uint32_t)(wm * 32 + (lane & 15));
    uint32_t a_colb = (uint32_t)((lane >> 4) * 16);
    uint32_t b_row  = (uint32_t)(wn * 64 + (lane & 7));
    uint32_t b_colb = (uint32_t)((lane >> 3) * 16);

    for (int c = 0; c < 24; c++) {
        if (c < 23) asm volatile("cp.async.wait_group 1;" ::: "memory");
        else        asm volatile("cp.async.wait_group 0;" ::: "memory");
        __syncthreads();
        if (c + 2 < 24) issue(c + 2);

        int buf = c % NST;
        uint32_t sA = sbase + (uint32_t)buf * BUFB;
        uint32_t sB = sbase + (uint32_t)(NST + buf) * BUFB;

        #pragma unroll
        for (int kh = 0; kh < 2; kh++) {
            uint32_t bf[8][4];
            #pragma unroll
            for (int nt = 0; nt < 8; nt++)
                ldsm4(bf[nt], sB + (b_row + nt * 8) * ROWB + kh * 64 + b_colb);

            #pragma unroll
            for (int ks = 0; ks < 2; ks++) {
                uint32_t af[2][4];
                ldsm4(af[0], sA + a_row * ROWB + kh * 64 + ks * 32 + a_colb);
                ldsm4(af[1], sA + (a_row + 16) * ROWB + kh * 64 + ks * 32 + a_colb);
                #pragma unroll
                for (int mi = 0; mi < 2; mi++)
                    #pragma unroll
                    for (int nt = 0; nt < 8; nt++)
                        mma_bf16(acc[mi][nt], af[mi], bf[nt][2 * ks], bf[nt][2 * ks + 1]);
            }
        }
    }

    int gid = lane >> 2, tig = lane & 3;
    float bv[16];
    #pragma unroll
    for (int nt = 0; nt < 8; nt++) {
        int col = n0 + wn * 64 + nt * 8 + 2 * tig;
        bv[nt * 2]     = bias[col];
        bv[nt * 2 + 1] = bias[col + 1];
    }
    #pragma unroll
    for (int mi = 0; mi < 2; mi++) {
        int mrow = m0 + wm * 32 + mi * 16 + gid;
        #pragma unroll
        for (int nt = 0; nt < 8; nt++) {
            int col = n0 + wn * 64 + nt * 8 + 2 * tig;
            float v0 = acc[mi][nt][0] + bv[nt * 2];
            float v1 = acc[mi][nt][1] + bv[nt * 2 + 1];
            float v2 = acc[mi][nt][2] + bv[nt * 2];
            float v3 = acc[mi][nt][3] + bv[nt * 2 + 1];
            if (mode == 0) {
                float* C = (float*)Cout;
                float2 p0 = {v0, v1}, p1 = {v2, v3};
                *(float2*)&C[(size_t)mrow * Ntot + col]       = p0;
                *(float2*)&C[(size_t)(mrow + 8) * Ntot + col] = p1;
            } else {
                __nv_bfloat16* C = (__nv_bfloat16*)Cout;
                v0 = tanhf(v0); v1 = tanhf(v1); v2 = tanhf(v2); v3 = tanhf(v3);
                __nv_bfloat16 h0 = __float2bfloat16(v0), h1 = __float2bfloat16(v1);
                __nv_bfloat16 h2 = __float2bfloat16(v2), h3 = __float2bfloat16(v3);
                __nv_bfloat16 l0 = __float2bfloat16(v0 - __bfloat162float(h0));
                __nv_bfloat16 l1 = __float2bfloat16(v1 - __bfloat162float(h1));
                __nv_bfloat16 l2 = __float2bfloat16(v2 - __bfloat162float(h2));
                __nv_bfloat16 l3 = __float2bfloat16(v3 - __bfloat162float(h3));
                __nv_bfloat162 ph0 = {h0, h1}, ph1 = {h2, h3};
                __nv_bfloat162 pl0 = {l0, l1}, pl1 = {l2, l3};
                *(__nv_bfloat162*)&C[(size_t)mrow * 1024 + col]             = ph0;
                *(__nv_bfloat162*)&C[(size_t)mrow * 1024 + 512 + col]       = pl0;
                *(__nv_bfloat162*)&C[(size_t)(mrow + 8) * 1024 + col]       = ph1;
                *(__nv_bfloat162*)&C[(size_t)(mrow + 8) * 1024 + 512 + col] = pl1;
            }
        }
    }
}

// ---------------------------------------------------------------------------
// Persistent GRU scan: W-hi regs + bulk-DMA with split hi halves + deferred e2
// + release/acquire grid barrier (no threadfence).
// ---------------------------------------------------------------------------
#define SC_STRIDE 520                            // bf16 elems/row -> 1040 B
#define SC_W_BYTES (96 * SC_STRIDE * 2)          // 99840
#define SC_H_BYTES (64 * SC_STRIDE * 2)          // 66560
#define SC_GH_F    (48 * 33)
#define SCAN_SMEM_BYTES (SC_W_BYTES + SC_H_BYTES + SC_GH_F * 4 + 256)

__global__ void __launch_bounds__(256, 1)
k_scan(const float* __restrict__ Whh, const float* __restrict__ bhh) {
    extern __shared__ __align__(16) char dynsm[];
    __nv_bfloat16* ws  = (__nv_bfloat16*)dynsm;
    __nv_bfloat16* hsb = (__nv_bfloat16*)(dynsm + SC_W_BYTES);
    float* gh  = (float*)(dynsm + SC_W_BYTES + SC_H_BYTES);
    float* bsh = gh + SC_GH_F;
    uint32_t ws_u = smem_u32(ws);
    uint32_t hs_u = smem_u32(hsb);
    uint32_t mbA1 = smem_u32(dynsm + SC_W_BYTES + SC_H_BYTES + SC_GH_F * 4 + 192);
    uint32_t mbA2 = mbA1 + 8;
    uint32_t mbB  = mbA1 + 16;

    int tid = threadIdx.x, wid = tid >> 5, lane = tid & 31;
    int blk = blockIdx.x;
    int bg = blk >> 5, dg = blk & 31;
    int d0 = dg << 4, b0 = bg << 5;

    // Load W slice once, split into bf16 hi/lo plane rows.
    for (int i = tid; i < 48 * 512; i += 256) {
        int j = i >> 9, k = i & 511;            // j = gate*16 + dc
        int g = j >> 4, dc = j & 15;
        float w = Whh[(size_t)(g * 512 + d0 + dc) * 512 + k];
        __nv_bfloat16 hi = __float2bfloat16(w);
        __nv_bfloat16 lo = __float2bfloat16(w - __bfloat162float(hi));
        ws[j * SC_STRIDE + k]        = hi;
        ws[(48 + j) * SC_STRIDE + k] = lo;
    }
    if (tid < 48) bsh[tid] = bhh[(tid >> 4) * 512 + d0 + (tid & 15)];
    if (tid == 0) { mbar_init(mbA1, 1); mbar_init(mbA2, 1); mbar_init(mbB, 1); }
    __syncthreads();

    int mt = wid % 3, nh = wid / 3;             // mma mapping (wid < 6)
    uint32_t aw_hi = ws_u + (uint32_t)((mt * 16 + (lane & 15)) * 1040)
                   + ((lane >> 4) << 4);
    uint32_t aw_lo = aw_hi + 48u * 1040u;
    uint32_t bh_hi = hs_u + (uint32_t)((nh * 16 + (lane & 7)) * 1040)
                   + ((lane >> 3) << 4);
    uint32_t bh_lo = bh_hi + 32u * 1040u;
    uint32_t mbHi = (nh == 0) ? mbA1 : mbA2;    // per-warp hi-half barrier

    // Hoist W-hi fragments into registers (loop-invariant across 256 steps).
    uint32_t ahr[16][2][4];
    if (wid < 6) {
        #pragma unroll
        for (int k32 = 0; k32 < 16; k32++) {
            ldsm4(ahr[k32][0], aw_hi + (k32 << 6));
            ldsm4(ahr[k32][1], aw_hi + (k32 << 6) + 32);
        }
    }

    int bi_a = tid >> 4;                        // epilogue: batches bi_a, +16
    int dc_a = tid & 15;
    int d_a = d0 + dc_a;
    int p = 0;

    for (int t = 0; t < HALF_T; t++) {
        // prefetch gx gate values (overlaps DMA)
        size_t rowA = ((size_t)(b0 + bi_a) * 256 + t) * 1536;
        size_t rowB = ((size_t)(b0 + bi_a + 16) * 256 + t) * 1536;
        float gxrA = __ldcg(g_gx + rowA + d_a);
        float gxzA = __ldcg(g_gx + rowA + 512 + d_a);
        float gxnA = __ldcg(g_gx + rowA + 1024 + d_a);
        float gxrB = __ldcg(g_gx + rowB + d_a);
        float gxzB = __ldcg(g_gx + rowB + 512 + d_a);
        float gxnB = __ldcg(g_gx + rowB + 1024 + d_a);

        // bulk-DMA stage h planes: hi half 1, hi half 2, lo block
        if (tid == 0) {
            const __nv_bfloat16* src = g_h2 + ((size_t)p * 4 + bg) * HGRP;
            mbar_expect(mbA1, 16640u);
            mbar_expect(mbA2, 16640u);
            mbar_expect(mbB,  33280u);
            bulkcp(hs_u,          src,         16640u, mbA1);
            bulkcp(hs_u + 16640u, src + 8320,  16640u, mbA2);
            bulkcp(hs_u + 33280u, src + 16640, 33280u, mbB);
        }

        // hi phase: (Whi + Wlo) x h_hi — each warp waits only its hi half
        float acc[2][4];
        if (wid < 6) {
            mbar_wait(mbHi, (uint32_t)(t & 1));
            #pragma unroll
            for (int nt = 0; nt < 2; nt++)
                #pragma unroll
                for (int q = 0; q < 4; q++) acc[nt][q] = 0.0f;
            #pragma unroll
            for (int k32 = 0; k32 < 16; k32++) {
                int kb = k32 << 6;
                uint32_t al0[4], al1[4], bf0[4], bf1[4];
                ldsm4(al0, aw_lo + kb);
                ldsm4(al1, aw_lo + kb + 32);
                ldsm4(bf0, bh_hi + kb);
                ldsm4(bf1, bh_hi + kb + 8 * 1040);
                mma_bf16(acc[0], ahr[k32][0], bf0[0], bf0[1]);
                mma_bf16(acc[1], ahr[k32][0], bf1[0], bf1[1]);
                mma_bf16(acc[0], ahr[k32][1], bf0[2], bf0[3]);
                mma_bf16(acc[1], ahr[k32][1], bf1[2], bf1[3]);
                mma_bf16(acc[0], al0, bf0[0], bf0[1]);
                mma_bf16(acc[1], al0, bf1[0], bf1[1]);
                mma_bf16(acc[0], al1, bf0[2], bf0[3]);
                mma_bf16(acc[1], al1, bf1[2], bf1[3]);
            }
            mbar_wait(mbB, (uint32_t)(t & 1));  // lo plane visible
            #pragma unroll
            for (int k32 = 0; k32 < 16; k32++) {
                int kb = k32 << 6;
                uint32_t bl0[4], bl1[4];
                ldsm4(bl0, bh_lo + kb);
                ldsm4(bl1, bh_lo + kb + 8 * 1040);
                mma_bf16(acc[0], ahr[k32][0], bl0[0], bl0[1]);
                mma_bf16(acc[1], ahr[k32][0], bl1[0], bl1[1]);
                mma_bf16(acc[0], ahr[k32][1], bl0[2], bl0[3]);
                mma_bf16(acc[1], ahr[k32][1], bl1[2], bl1[3]);
            }
            // write gh fragments
            int r = lane >> 2, c = (lane & 3) << 1;
            #pragma unroll
            for (int nt = 0; nt < 2; nt++) {
                int n = nh * 16 + nt * 8 + c;
                int m = mt * 16 + r;
                gh[m * 33 + n]           = acc[nt][0];
                gh[m * 33 + n + 1]       = acc[nt][1];
                gh[(m + 8) * 33 + n]     = acc[nt][2];
                gh[(m + 8) * 33 + n + 1] = acc[nt][3];
            }
        }
        // visibility chain: warps 0-2 acquired mbA1, warps 3-5 acquired
        // mbA2 + all acquired mbB; this syncthreads makes all three
        // DMA blocks visible to every thread for the epilogue.
        __syncthreads();

        // epilogue: 2 outputs per thread; h stores on the release path,
        // e2 stores deferred past the barrier arrive.
        __nv_bfloat16 ehi[2], elo[2];
        #pragma unroll
        for (int half = 0; half < 2; half++) {
            int bi = bi_a + (half << 4);
            float gxr = half ? gxrB : gxrA;
            float gxz = half ? gxzB : gxzA;
            float gxn = half ? gxnB : gxnA;
            float ghr = gh[dc_a * 33 + bi]        + bsh[dc_a];
            float ghz = gh[(16 + dc_a) * 33 + bi] + bsh[16 + dc_a];
            float ghn = gh[(32 + dc_a) * 33 + bi] + bsh[32 + dc_a];
            float r = 1.0f / (1.0f + __expf(-(gxr + ghr)));
            float z = 1.0f / (1.0f + __expf(-(gxz + ghz)));
            float n = tanhf(gxn + r * ghn);
            float hold = __bfloat162float(hsb[bi * SC_STRIDE + d_a])
                       + __bfloat162float(hsb[(32 + bi) * SC_STRIDE + d_a]);
            float hn = (1.0f - z) * n + z * hold;
            __nv_bfloat16 hi = __float2bfloat16(hn);
            __nv_bfloat16 lo = __float2bfloat16(hn - __bfloat162float(hi));
            ehi[half] = hi; elo[half] = lo;
            if (t < HALF_T - 1) {
                size_t gb = ((size_t)(p ^ 1) * 4 + bg) * HGRP;
                g_h2[gb + bi * HROW + d_a]         = hi;
                g_h2[gb + 16640 + bi * HROW + d_a] = lo;
            }
        }

        if (t < HALF_T - 1) {
            __syncthreads();                     // all h stores issued
            if (tid == 0) arrive_release(&g_ctr4[bg * 32]);
        }

        // e2 stores overlap the peer wait
        #pragma unroll
        for (int half = 0; half < 2; half++) {
            int bi = bi_a + (half << 4);
            size_t erow = ((size_t)(b0 + bi) * 256 + t) * 1024;
            g_e2[erow + d_a]       = ehi[half];
            g_e2[erow + 512 + d_a] = elo[half];
        }

        if (t < HALF_T - 1) {
            if (tid == 0) {
                unsigned target = (unsigned)(t + 1) * 32u;
                while (ld_acquire(&g_ctr4[bg * 32]) < target) { }
            }
            __syncthreads();
        }
        p ^= 1;
    }
}

// ---------------------------------------------------------------------------
// Fused head: out[m] = logsoftmax(f[m]) @ W_comb^T + b_comb
// ---------------------------------------------------------------------------
__global__ void __launch_bounds__(256)
k_final(const float* __restrict__ X, float* __restrict__ out) {
    __shared__ float Wc[NCLS * DD];
    __shared__ float ss[NCLS], bc[NCLS];
    int tid = threadIdx.x;
    for (int idx = tid; idx < NCLS * DD; idx += 256) Wc[idx] = g_Wc[idx];
    if (tid < NCLS) { ss[tid] = g_s[tid]; bc[tid] = g_bc[tid]; }
    __syncthreads();

    int w = tid >> 5, l = tid & 31;
    int m = (blockIdx.x << 3) + w;
    const float* xr = X + (size_t)m * DD;

    float f[16];
    #pragma unroll
    for (int i = 0; i < 16; i++) f[i] = xr[i * 32 + l];

    float mx = f[0];
    #pragma unroll
    for (int i = 1; i < 16; i++) mx = fmaxf(mx, f[i]);
    #pragma unroll
    for (int off = 16; off > 0; off >>= 1)
        mx = fmaxf(mx, __shfl_xor_sync(0xffffffffu, mx, off));

    float se = 0.0f;
    #pragma unroll
    for (int i = 0; i < 16; i++) se += __expf(f[i] - mx);
    #pragma unroll
    for (int off = 16; off > 0; off >>= 1)
        se += __shfl_xor_sync(0xffffffffu, se, off);
    float c = mx + __logf(se);

    #pragma unroll
    for (int n = 0; n < NCLS; n++) {
        float dot = 0.0f;
        const float* wr = Wc + n * DD;
        #pragma unroll
        for (int i = 0; i < 16; i++) dot += f[i] * wr[i * 32 + l];
        #pragma unroll
        for (int off = 16; off > 0; off >>= 1)
            dot += __shfl_xor_sync(0xffffffffu, dot, off);
        if (l == 0) out[m * NCLS + n] = dot - c * ss[n] + bc[n];
    }
}

// ---------------------------------------------------------------------------
// kernel_launch — ordered so k_scan is launch index 5 (ncu -s 5 -c 1 target)
// ---------------------------------------------------------------------------
extern "C" void kernel_launch(void* const* d_in, const int* in_sizes, int n_in,
                              void* d_out, int out_size) {
    (void)in_sizes; (void)out_size;
    if (n_in < 17) return;
    const float* x0     = (const float*)d_in[0];
    const float* W_ih   = (const float*)d_in[3];
    const float* W_hh   = (const float*)d_in[4];
    const float* b_ih   = (const float*)d_in[5];
    const float* b_hh   = (const float*)d_in[6];
    const float* W1     = (const float*)d_in[7];
    const float* bb1    = (const float*)d_in[8];
    const float* W2     = (const float*)d_in[9];
    const float* bb2    = (const float*)d_in[10];
    const float* W3     = (const float*)d_in[11];
    const float* bb3    = (const float*)d_in[12];
    const float* W_half = (const float*)d_in[13];
    const float* b_half = (const float*)d_in[14];
    const float* W_out  = (const float*)d_in[15];
    const float* b_out  = (const float*)d_in[16];
    float* out = (float*)d_out;

    float *gx, *x3;
    __nv_bfloat16 *A0, *e2, *x1b, *x2b, *Wih2, *W12, *W22, *W32;
    cudaGetSymbolAddress((void**)&gx,   g_gx);
    cudaGetSymbolAddress((void**)&x3,   g_x3);
    cudaGetSymbolAddress((void**)&A0,   g_A0);
    cudaGetSymbolAddress((void**)&e2,   g_e2);
    cudaGetSymbolAddress((void**)&x1b,  g_x1b);
    cudaGetSymbolAddress((void**)&x2b,  g_x2b);
    cudaGetSymbolAddress((void**)&Wih2, g_Wih2);
    cudaGetSymbolAddress((void**)&W12,  g_W12);
    cudaGetSymbolAddress((void**)&W22,  g_W22);
    cudaGetSymbolAddress((void**)&W32,  g_W32);

    cudaFuncSetAttribute(k_scan, cudaFuncAttributeMaxDynamicSharedMemorySize,
                         SCAN_SMEM_BYTES);
    cudaFuncSetAttribute(k_mma_gemm, cudaFuncAttributeMaxDynamicSharedMemorySize,
                         GEMM_SMEM);

    // 0,1: input/weight splits needed by gx GEMM
    k_split<<<(MROWS * 128) / 256, 256>>>(x0, A0, MROWS, 1);
    k_split<<<(1536 * 128) / 256, 256>>>(W_ih, Wih2, 1536, 0);
    // 2: init h planes + barrier counters
    k_init<<<520, 256>>>();
    // 3: gx = x0 @ W_ih^T + b_ih   [32768 x 1536]  (128x128 tiles, BK=64)
    k_mma_gemm<<<256 * 12, 256, GEMM_SMEM>>>(A0, Wih2, b_ih, gx, 1536, 12, 0);
    // 4: head fold (independent)
    k_prep1<<<14, 256>>>(W_half, W_out);
    // 5: GRU scan (PROFILED)
    k_scan<<<128, 256, SCAN_SMEM_BYTES>>>(W_hh, b_hh);
    // 6: head fold part 2
    k_prep2<<<1, 256>>>(W_out, b_half, b_out);
    // 7: merged FFN weight splits
    k_splitW<<<768, 256>>>(W1, W2, W3);
    // 8-10: FFN (128x128 tiles, BK=64)
    k_mma_gemm<<<256 * 4, 256, GEMM_SMEM>>>(e2,  W12, bb1, x1b, 512, 4, 1);
    k_mma_gemm<<<256 * 4, 256, GEMM_SMEM>>>(x1b, W22, bb2, x2b, 512, 4, 1);
    k_mma_gemm<<<256 * 4, 256, GEMM_SMEM>>>(x2b, W32, bb3, x3,  512, 4, 0);
    // 11: fused log_softmax + combined classifier head
    k_final<<<MROWS / 8, 256>>>(x3, out);
}

// round 16
// speedup vs baseline: 1.2878x; 1.0029x over previous
#include <cuda_runtime.h>
#include <cuda_bf16.h>
#include <cstddef>
#include <cstdint>

// Problem constants
#define BB     128
#define TT     512
#define HALF_T 256
#define DD     512
#define NCLS   7
#define MROWS  (BB * HALF_T)   // 32768 rows fed to FFN / head

typedef unsigned long long ull;

// ---------------------------------------------------------------------------
// mma.sync / ldmatrix / cp.async / bulk-DMA helpers (baseline PTX, sm_100-safe)
// ---------------------------------------------------------------------------
__device__ __forceinline__ uint32_t smem_u32(const void* p) {
    uint32_t a;
    asm("{ .reg .u64 t; cvta.to.shared.u64 t, %1; cvt.u32.u64 %0, t; }"
        : "=r"(a) : "l"(p));
    return a;
}
__device__ __forceinline__ void ldsm4(uint32_t* r, uint32_t addr) {
    asm volatile("ldmatrix.sync.aligned.m8n8.x4.shared.b16 {%0,%1,%2,%3}, [%4];"
        : "=r"(r[0]), "=r"(r[1]), "=r"(r[2]), "=r"(r[3]) : "r"(addr));
}
__device__ __forceinline__ void mma_bf16(float* d, const uint32_t* a,
                                         uint32_t b0, uint32_t b1) {
    asm volatile("mma.sync.aligned.m16n8k16.row.col.f32.bf16.bf16.f32 "
        "{%0,%1,%2,%3}, {%4,%5,%6,%7}, {%8,%9}, {%0,%1,%2,%3};"
        : "+f"(d[0]), "+f"(d[1]), "+f"(d[2]), "+f"(d[3])
        : "r"(a[0]), "r"(a[1]), "r"(a[2]), "r"(a[3]), "r"(b0), "r"(b1));
}
__device__ __forceinline__ void cpasync16(uint32_t dst, const void* src) {
    asm volatile("cp.async.cg.shared.global [%0], [%1], 16;"
                 :: "r"(dst), "l"(src));
}
#define CP_COMMIT() asm volatile("cp.async.commit_group;" ::: "memory")

// bulk DMA: gmem -> smem, completion via mbarrier complete_tx
__device__ __forceinline__ void bulkcp(uint32_t dst, const void* src,
                                       uint32_t bytes, uint32_t mbar) {
    asm volatile(
        "cp.async.bulk.shared::cluster.global.mbarrier::complete_tx::bytes "
        "[%0], [%1], %2, [%3];"
        :: "r"(dst), "l"(src), "r"(bytes), "r"(mbar) : "memory");
}
__device__ __forceinline__ void mbar_init(uint32_t mbar, uint32_t cnt) {
    asm volatile("mbarrier.init.shared.b64 [%0], %1;"
                 :: "r"(mbar), "r"(cnt) : "memory");
}
__device__ __forceinline__ void mbar_expect(uint32_t mbar, uint32_t bytes) {
    asm volatile("mbarrier.arrive.expect_tx.shared.b64 _, [%0], %1;"
                 :: "r"(mbar), "r"(bytes) : "memory");
}
__device__ __forceinline__ void mbar_wait(uint32_t mbar, uint32_t parity) {
    asm volatile("{\n\t.reg .pred P;\n\tWL%=:\n\t"
                 "mbarrier.try_wait.parity.acquire.cta.shared::cta.b64 P, [%0], %1;\n\t"
                 "@!P bra WL%=;\n\t}" :: "r"(mbar), "r"(parity) : "memory");
}
__device__ __forceinline__ void arrive_release(unsigned* ctr) {
    unsigned old;
    asm volatile("atom.release.gpu.global.add.u32 %0, [%1], 1;"
                 : "=r"(old) : "l"(ctr) : "memory");
}
__device__ __forceinline__ unsigned ld_acquire(const unsigned* ctr) {
    unsigned v;
    asm volatile("ld.acquire.gpu.global.u32 %0, [%1];"
                 : "=r"(v) : "l"(ctr) : "memory");
    return v;
}

// ---------------------------------------------------------------------------
// Device scratch
// ---------------------------------------------------------------------------
__device__ float g_gx[MROWS * 1536];             // input projections (fp32)
__device__ float g_x3[MROWS * DD];               // FFN layer-3 output (fp32)
__device__ __nv_bfloat16 g_A0 [MROWS * 1024];    // x0 split planes (hi|lo)
__device__ __nv_bfloat16 g_e2 [MROWS * 1024];    // emotions split planes
__device__ __nv_bfloat16 g_x1b[MROWS * 1024];
__device__ __nv_bfloat16 g_x2b[MROWS * 1024];
__device__ __nv_bfloat16 g_Wih2[1536 * 1024];    // weight split planes
__device__ __nv_bfloat16 g_W12 [512 * 1024];
__device__ __nv_bfloat16 g_W22 [512 * 1024];
__device__ __nv_bfloat16 g_W32 [512 * 1024];
// GRU h planes, padded layout for bulk DMA:
// [2 bufs][4 groups][2 planes][32 batches][520]  (row = plane*32+batch)
#define HROW 520
#define HGRP (2 * 32 * HROW)                     // 33280 elems / 66560 B
__device__ __nv_bfloat16 g_h2[2 * 4 * HGRP];
__device__ float g_Wc[NCLS * DD];
__device__ unsigned g_ctr4[4 * 32];              // barrier counters, 128B apart

// ---------------------------------------------------------------------------
// split helper: fp32 row chunk -> bf16 hi/lo planes
// ---------------------------------------------------------------------------
__device__ __forceinline__ void split_row(const float* src, __nv_bfloat16* dst,
                                          size_t so, size_t dro, int c4) {
    float4 v = *(const float4*)(src + so + c4);
    __nv_bfloat16 h[4], lo[4];
    float vv[4] = {v.x, v.y, v.z, v.w};
    #pragma unroll
    for (int i = 0; i < 4; i++) {
        h[i] = __float2bfloat16(vv[i]);
        lo[i] = __float2bfloat16(vv[i] - __bfloat162float(h[i]));
    }
    *(ull*)(dst + dro + c4)       = *(ull*)h;
    *(ull*)(dst + dro + 512 + c4) = *(ull*)lo;
}

// ---------------------------------------------------------------------------
// k_pre: ALL preprocessing in one launch.
//   ranges: [0, 4194304)               x0 split (perm row map)
//           [4194304, 4390912)         W_ih split (1536 rows)
//           [4390912, 4587520)         W1/W2/W3 splits (3 x 512 rows)
//           [4587520, 4654080)         h plane zero (bf162 units)
//           [4654080, 4657664)         Wc = W_out @ W_half (7*512)
//           [4657664, 4657668)         barrier counters
// ---------------------------------------------------------------------------
#define PRE_X0   (MROWS * 128)                   // 4194304
#define PRE_WIH  (PRE_X0 + 1536 * 128)           // 4390912
#define PRE_W123 (PRE_WIH + 3 * 512 * 128)       // 4587520
#define PRE_HZ   (PRE_W123 + 4 * HGRP / 2)       // 4654080
#define PRE_WC   (PRE_HZ + NCLS * DD)            // 4657664
#define PRE_END  (PRE_WC + 4)                    // 4657668
#define PRE_BLOCKS ((PRE_END + 255) / 256)

__global__ void k_pre(const float* __restrict__ x0,
                      const float* __restrict__ W_ih,
                      const float* __restrict__ W1,
                      const float* __restrict__ W2,
                      const float* __restrict__ W3,
                      const float* __restrict__ W_half,
                      const float* __restrict__ W_out) {
    int idx = blockIdx.x * 256 + threadIdx.x;
    if (idx < PRE_X0) {
        int r = idx >> 7, c4 = (idx & 127) << 2;
        size_t so = (size_t)((r >> 8) * 512 + (r & 255)) * 512;
        split_row(x0, g_A0, so, (size_t)r * 1024, c4);
    } else if (idx < PRE_WIH) {
        int u = idx - PRE_X0;
        int r = u >> 7, c4 = (u & 127) << 2;
        split_row(W_ih, g_Wih2, (size_t)r * 512, (size_t)r * 1024, c4);
    } else if (idx < PRE_W123) {
        int u = idx - PRE_WIH;
        int which = u / (512 * 128);
        int rem = u - which * (512 * 128);
        int r = rem >> 7, c4 = (rem & 127) << 2;
        const float* src = (which == 0) ? W1 : (which == 1) ? W2 : W3;
        __nv_bfloat16* dst = (which == 0) ? g_W12 : (which == 1) ? g_W22 : g_W32;
        split_row(src, dst, (size_t)r * 512, (size_t)r * 1024, c4);
    } else if (idx < PRE_HZ) {
        int u = idx - PRE_W123;
        ((__nv_bfloat162*)g_h2)[u] = __nv_bfloat162{__nv_bfloat16(0.f),
                                                    __nv_bfloat16(0.f)};
    } else if (idx < PRE_WC) {
        int u = idx - PRE_HZ;
        int n = u / DD, k = u - n * DD;
        float s = 0.0f;
        for (int j = 0; j < 256; j++)
            s += W_out[n * 256 + j] * W_half[j * DD + k];
        g_Wc[u] = s;
    } else if (idx < PRE_END) {
        g_ctr4[(idx - PRE_WC) * 32] = 0u;
    }
}

// ---------------------------------------------------------------------------
// mma.sync bf16-split GEMM, 128x128 tile, BK=64 (24 chunks), 3-stage pipeline
// (exact R14/R15 config — proven 469-495 us on gx).
// ---------------------------------------------------------------------------
#define ROWB 144         // padded smem row: 64 bf16 (128B) + 16B pad
#define BUFB (128 * ROWB)    // 18432
#define NST  3
#define GEMM_SMEM (2 * NST * BUFB)   // 110592

__global__ void __launch_bounds__(256, 2)
k_mma_gemm(const __nv_bfloat16* __restrict__ A,
           const __nv_bfloat16* __restrict__ Bw,
           const float* __restrict__ bias,
           void* __restrict__ Cout,
           int Ntot, int n_tiles, int mode) {
    extern __shared__ __align__(16) char smc[];
    uint32_t sbase = smem_u32(smc);
    int tid = threadIdx.x, wid = tid >> 5, lane = tid & 31;
    int m0 = (blockIdx.x / n_tiles) << 7;
    int n0 = (blockIdx.x % n_tiles) << 7;

    int sr2 = tid >> 3;          // staging row (0..31), +32/+64/+96
    int sc2 = tid & 7;           // 16B column chunk (0..7 => 128B row)

    float acc[2][8][4];
    #pragma unroll
    for (int i = 0; i < 2; i++)
        #pragma unroll
        for (int j = 0; j < 8; j++)
            #pragma unroll
            for (int q = 0; q < 4; q++) acc[i][j][q] = 0.0f;

    auto issue = [&](int c) {
        int seg = c >> 3, kofs = (c & 7) << 6;
        int asel = (seg == 1) ? 512 : 0;
        int bsel = (seg == 2) ? 512 : 0;
        const __nv_bfloat16* Ag = A + (size_t)m0 * 1024 + asel + kofs;
        const __nv_bfloat16* Bg = Bw + (size_t)n0 * 1024 + bsel + kofs;
        int buf = c % NST;
        uint32_t da = sbase + (uint32_t)buf * BUFB;
        uint32_t db = sbase + (uint32_t)(NST + buf) * BUFB;
        #pragma unroll
        for (int rr = 0; rr < 4; rr++) {
            int row = sr2 + rr * 32;
            cpasync16(da + row * ROWB + sc2 * 16, Ag + (size_t)row * 1024 + sc2 * 8);
            cpasync16(db + row * ROWB + sc2 * 16, Bg + (size_t)row * 1024 + sc2 * 8);
        }
        CP_COMMIT();
    };

    issue(0);
    issue(1);

    int wm = wid & 3;
    int wn = wid >> 2;
    uint32_t a_row  = (uint32_t)(wm * 32 + (lane & 15));
    uint32_t a_colb = (uint32_t)((lane >> 4) * 16);
    uint32_t b_row  = (uint32_t)(wn * 64 + (lane & 7));
    uint32_t b_colb = (uint32_t)((lane >> 3) * 16);

    for (int c = 0; c < 24; c++) {
        if (c < 23) asm volatile("cp.async.wait_group 1;" ::: "memory");
        else        asm volatile("cp.async.wait_group 0;" ::: "memory");
        __syncthreads();
        if (c + 2 < 24) issue(c + 2);

        int buf = c % NST;
        uint32_t sA = sbase + (uint32_t)buf * BUFB;
        uint32_t sB = sbase + (uint32_t)(NST + buf) * BUFB;

        #pragma unroll
        for (int kh = 0; kh < 2; kh++) {
            uint32_t bf[8][4];
            #pragma unroll
            for (int nt = 0; nt < 8; nt++)
                ldsm4(bf[nt], sB + (b_row + nt * 8) * ROWB + kh * 64 + b_colb);

            #pragma unroll
            for (int ks = 0; ks < 2; ks++) {
                uint32_t af[2][4];
                ldsm4(af[0], sA + a_row * ROWB + kh * 64 + ks * 32 + a_colb);
                ldsm4(af[1], sA + (a_row + 16) * ROWB + kh * 64 + ks * 32 + a_colb);
                #pragma unroll
                for (int mi = 0; mi < 2; mi++)
                    #pragma unroll
                    for (int nt = 0; nt < 8; nt++)
                        mma_bf16(acc[mi][nt], af[mi], bf[nt][2 * ks], bf[nt][2 * ks + 1]);
            }
        }
    }

    int gid = lane >> 2, tig = lane & 3;
    float bv[16];
    #pragma unroll
    for (int nt = 0; nt < 8; nt++) {
        int col = n0 + wn * 64 + nt * 8 + 2 * tig;
        bv[nt * 2]     = bias[col];
        bv[nt * 2 + 1] = bias[col + 1];
    }
    #pragma unroll
    for (int mi = 0; mi < 2; mi++) {
        int mrow = m0 + wm * 32 + mi * 16 + gid;
        #pragma unroll
        for (int nt = 0; nt < 8; nt++) {
            int col = n0 + wn * 64 + nt * 8 + 2 * tig;
            float v0 = acc[mi][nt][0] + bv[nt * 2];
            float v1 = acc[mi][nt][1] + bv[nt * 2 + 1];
            float v2 = acc[mi][nt][2] + bv[nt * 2];
            float v3 = acc[mi][nt][3] + bv[nt * 2 + 1];
            if (mode == 0) {
                float* C = (float*)Cout;
                float2 p0 = {v0, v1}, p1 = {v2, v3};
                *(float2*)&C[(size_t)mrow * Ntot + col]       = p0;
                *(float2*)&C[(size_t)(mrow + 8) * Ntot + col] = p1;
            } else {
                __nv_bfloat16* C = (__nv_bfloat16*)Cout;
                v0 = tanhf(v0); v1 = tanhf(v1); v2 = tanhf(v2); v3 = tanhf(v3);
                __nv_bfloat16 h0 = __float2bfloat16(v0), h1 = __float2bfloat16(v1);
                __nv_bfloat16 h2 = __float2bfloat16(v2), h3 = __float2bfloat16(v3);
                __nv_bfloat16 l0 = __float2bfloat16(v0 - __bfloat162float(h0));
                __nv_bfloat16 l1 = __float2bfloat16(v1 - __bfloat162float(h1));
                __nv_bfloat16 l2 = __float2bfloat16(v2 - __bfloat162float(h2));
                __nv_bfloat16 l3 = __float2bfloat16(v3 - __bfloat162float(h3));
                __nv_bfloat162 ph0 = {h0, h1}, ph1 = {h2, h3};
                __nv_bfloat162 pl0 = {l0, l1}, pl1 = {l2, l3};
                *(__nv_bfloat162*)&C[(size_t)mrow * 1024 + col]             = ph0;
                *(__nv_bfloat162*)&C[(size_t)mrow * 1024 + 512 + col]       = pl0;
                *(__nv_bfloat162*)&C[(size_t)(mrow + 8) * 1024 + col]       = ph1;
                *(__nv_bfloat162*)&C[(size_t)(mrow + 8) * 1024 + 512 + col] = pl1;
            }
        }
    }
}

// ---------------------------------------------------------------------------
// Persistent GRU scan (exact R15 config: W-hi regs + split hi-half DMA +
// release/acquire barrier + deferred e2 stores).
// ---------------------------------------------------------------------------
#define SC_STRIDE 520                            // bf16 elems/row -> 1040 B
#define SC_W_BYTES (96 * SC_STRIDE * 2)          // 99840
#define SC_H_BYTES (64 * SC_STRIDE * 2)          // 66560
#define SC_GH_F    (48 * 33)
#define SCAN_SMEM_BYTES (SC_W_BYTES + SC_H_BYTES + SC_GH_F * 4 + 256)

__global__ void __launch_bounds__(256, 1)
k_scan(const float* __restrict__ Whh, const float* __restrict__ bhh) {
    extern __shared__ __align__(16) char dynsm[];
    __nv_bfloat16* ws  = (__nv_bfloat16*)dynsm;
    __nv_bfloat16* hsb = (__nv_bfloat16*)(dynsm + SC_W_BYTES);
    float* gh  = (float*)(dynsm + SC_W_BYTES + SC_H_BYTES);
    float* bsh = gh + SC_GH_F;
    uint32_t ws_u = smem_u32(ws);
    uint32_t hs_u = smem_u32(hsb);
    uint32_t mbA1 = smem_u32(dynsm + SC_W_BYTES + SC_H_BYTES + SC_GH_F * 4 + 192);
    uint32_t mbA2 = mbA1 + 8;
    uint32_t mbB  = mbA1 + 16;

    int tid = threadIdx.x, wid = tid >> 5, lane = tid & 31;
    int blk = blockIdx.x;
    int bg = blk >> 5, dg = blk & 31;
    int d0 = dg << 4, b0 = bg << 5;

    // Load W slice once, split into bf16 hi/lo plane rows.
    for (int i = tid; i < 48 * 512; i += 256) {
        int j = i >> 9, k = i & 511;            // j = gate*16 + dc
        int g = j >> 4, dc = j & 15;
        float w = Whh[(size_t)(g * 512 + d0 + dc) * 512 + k];
        __nv_bfloat16 hi = __float2bfloat16(w);
        __nv_bfloat16 lo = __float2bfloat16(w - __bfloat162float(hi));
        ws[j * SC_STRIDE + k]        = hi;
        ws[(48 + j) * SC_STRIDE + k] = lo;
    }
    if (tid < 48) bsh[tid] = bhh[(tid >> 4) * 512 + d0 + (tid & 15)];
    if (tid == 0) { mbar_init(mbA1, 1); mbar_init(mbA2, 1); mbar_init(mbB, 1); }
    __syncthreads();

    int mt = wid % 3, nh = wid / 3;             // mma mapping (wid < 6)
    uint32_t aw_hi = ws_u + (uint32_t)((mt * 16 + (lane & 15)) * 1040)
                   + ((lane >> 4) << 4);
    uint32_t aw_lo = aw_hi + 48u * 1040u;
    uint32_t bh_hi = hs_u + (uint32_t)((nh * 16 + (lane & 7)) * 1040)
                   + ((lane >> 3) << 4);
    uint32_t bh_lo = bh_hi + 32u * 1040u;
    uint32_t mbHi = (nh == 0) ? mbA1 : mbA2;    // per-warp hi-half barrier

    // Hoist W-hi fragments into registers (loop-invariant across 256 steps).
    uint32_t ahr[16][2][4];
    if (wid < 6) {
        #pragma unroll
        for (int k32 = 0; k32 < 16; k32++) {
            ldsm4(ahr[k32][0], aw_hi + (k32 << 6));
            ldsm4(ahr[k32][1], aw_hi + (k32 << 6) + 32);
        }
    }

    int bi_a = tid >> 4;                        // epilogue: batches bi_a, +16
    int dc_a = tid & 15;
    int d_a = d0 + dc_a;
    int p = 0;

    for (int t = 0; t < HALF_T; t++) {
        // prefetch gx gate values (overlaps DMA)
        size_t rowA = ((size_t)(b0 + bi_a) * 256 + t) * 1536;
        size_t rowB = ((size_t)(b0 + bi_a + 16) * 256 + t) * 1536;
        float gxrA = __ldcg(g_gx + rowA + d_a);
        float gxzA = __ldcg(g_gx + rowA + 512 + d_a);
        float gxnA = __ldcg(g_gx + rowA + 1024 + d_a);
        float gxrB = __ldcg(g_gx + rowB + d_a);
        float gxzB = __ldcg(g_gx + rowB + 512 + d_a);
        float gxnB = __ldcg(g_gx + rowB + 1024 + d_a);

        // bulk-DMA stage h planes: hi half 1, hi half 2, lo block
        if (tid == 0) {
            const __nv_bfloat16* src = g_h2 + ((size_t)p * 4 + bg) * HGRP;
            mbar_expect(mbA1, 16640u);
            mbar_expect(mbA2, 16640u);
            mbar_expect(mbB,  33280u);
            bulkcp(hs_u,          src,         16640u, mbA1);
            bulkcp(hs_u + 16640u, src + 8320,  16640u, mbA2);
            bulkcp(hs_u + 33280u, src + 16640, 33280u, mbB);
        }

        // hi phase: (Whi + Wlo) x h_hi — each warp waits only its hi half
        float acc[2][4];
        if (wid < 6) {
            mbar_wait(mbHi, (uint32_t)(t & 1));
            #pragma unroll
            for (int nt = 0; nt < 2; nt++)
                #pragma unroll
                for (int q = 0; q < 4; q++) acc[nt][q] = 0.0f;
            #pragma unroll
            for (int k32 = 0; k32 < 16; k32++) {
                int kb = k32 << 6;
                uint32_t al0[4], al1[4], bf0[4], bf1[4];
                ldsm4(al0, aw_lo + kb);
                ldsm4(al1, aw_lo + kb + 32);
                ldsm4(bf0, bh_hi + kb);
                ldsm4(bf1, bh_hi + kb + 8 * 1040);
                mma_bf16(acc[0], ahr[k32][0], bf0[0], bf0[1]);
                mma_bf16(acc[1], ahr[k32][0], bf1[0], bf1[1]);
                mma_bf16(acc[0], ahr[k32][1], bf0[2], bf0[3]);
                mma_bf16(acc[1], ahr[k32][1], bf1[2], bf1[3]);
                mma_bf16(acc[0], al0, bf0[0], bf0[1]);
                mma_bf16(acc[1], al0, bf1[0], bf1[1]);
                mma_bf16(acc[0], al1, bf0[2], bf0[3]);
                mma_bf16(acc[1], al1, bf1[2], bf1[3]);
            }
            mbar_wait(mbB, (uint32_t)(t & 1));  // lo plane visible
            #pragma unroll
            for (int k32 = 0; k32 < 16; k32++) {
                int kb = k32 << 6;
                uint32_t bl0[4], bl1[4];
                ldsm4(bl0, bh_lo + kb);
                ldsm4(bl1, bh_lo + kb + 8 * 1040);
                mma_bf16(acc[0], ahr[k32][0], bl0[0], bl0[1]);
                mma_bf16(acc[1], ahr[k32][0], bl1[0], bl1[1]);
                mma_bf16(acc[0], ahr[k32][1], bl0[2], bl0[3]);
                mma_bf16(acc[1], ahr[k32][1], bl1[2], bl1[3]);
            }
            // write gh fragments
            int r = lane >> 2, c = (lane & 3) << 1;
            #pragma unroll
            for (int nt = 0; nt < 2; nt++) {
                int n = nh * 16 + nt * 8 + c;
                int m = mt * 16 + r;
                gh[m * 33 + n]           = acc[nt][0];
                gh[m * 33 + n + 1]       = acc[nt][1];
                gh[(m + 8) * 33 + n]     = acc[nt][2];
                gh[(m + 8) * 33 + n + 1] = acc[nt][3];
            }
        }
        __syncthreads();

        // epilogue: 2 outputs per thread; h stores on the release path,
        // e2 stores deferred past the barrier arrive.
        __nv_bfloat16 ehi[2], elo[2];
        #pragma unroll
        for (int half = 0; half < 2; half++) {
            int bi = bi_a + (half << 4);
            float gxr = half ? gxrB : gxrA;
            float gxz = half ? gxzB : gxzA;
            float gxn = half ? gxnB : gxnA;
            float ghr = gh[dc_a * 33 + bi]        + bsh[dc_a];
            float ghz = gh[(16 + dc_a) * 33 + bi] + bsh[16 + dc_a];
            float ghn = gh[(32 + dc_a) * 33 + bi] + bsh[32 + dc_a];
            float r = 1.0f / (1.0f + __expf(-(gxr + ghr)));
            float z = 1.0f / (1.0f + __expf(-(gxz + ghz)));
            float n = tanhf(gxn + r * ghn);
            float hold = __bfloat162float(hsb[bi * SC_STRIDE + d_a])
                       + __bfloat162float(hsb[(32 + bi) * SC_STRIDE + d_a]);
            float hn = (1.0f - z) * n + z * hold;
            __nv_bfloat16 hi = __float2bfloat16(hn);
            __nv_bfloat16 lo = __float2bfloat16(hn - __bfloat162float(hi));
            ehi[half] = hi; elo[half] = lo;
            if (t < HALF_T - 1) {
                size_t gb = ((size_t)(p ^ 1) * 4 + bg) * HGRP;
                g_h2[gb + bi * HROW + d_a]         = hi;
                g_h2[gb + 16640 + bi * HROW + d_a] = lo;
            }
        }

        if (t < HALF_T - 1) {
            __syncthreads();                     // all h stores issued
            if (tid == 0) arrive_release(&g_ctr4[bg * 32]);
        }

        // e2 stores overlap the peer wait
        #pragma unroll
        for (int half = 0; half < 2; half++) {
            int bi = bi_a + (half << 4);
            size_t erow = ((size_t)(b0 + bi) * 256 + t) * 1024;
            g_e2[erow + d_a]       = ehi[half];
            g_e2[erow + 512 + d_a] = elo[half];
        }

        if (t < HALF_T - 1) {
            if (tid == 0) {
                unsigned target = (unsigned)(t + 1) * 32u;
                while (ld_acquire(&g_ctr4[bg * 32]) < target) { }
            }
            __syncthreads();
        }
        p ^= 1;
    }
}

// ---------------------------------------------------------------------------
// Fused head: out[m] = logsoftmax(f[m]) @ W_comb^T + b_comb
//   ss/bc (formerly prep2) computed per block from staged Wc + gmem.
// ---------------------------------------------------------------------------
__global__ void __launch_bounds__(256)
k_final(const float* __restrict__ X,
        const float* __restrict__ W_out,
        const float* __restrict__ b_half,
        const float* __restrict__ b_out,
        float* __restrict__ out) {
    __shared__ float Wc[NCLS * DD];
    __shared__ float ss[NCLS], bc[NCLS];
    int tid = threadIdx.x;
    for (int idx = tid; idx < NCLS * DD; idx += 256) Wc[idx] = g_Wc[idx];
    __syncthreads();

    int w = tid >> 5, l = tid & 31;
    // inline prep2: warp w < 7 computes ss[w] (rowsum of Wc) and bc[w]
    if (w < NCLS) {
        float s = 0.0f;
        #pragma unroll
        for (int i = 0; i < 16; i++) s += Wc[w * DD + i * 32 + l];
        float b = 0.0f;
        #pragma unroll
        for (int i = 0; i < 8; i++)
            b += W_out[w * 256 + i * 32 + l] * b_half[i * 32 + l];
        #pragma unroll
        for (int off = 16; off > 0; off >>= 1) {
            s += __shfl_xor_sync(0xffffffffu, s, off);
            b += __shfl_xor_sync(0xffffffffu, b, off);
        }
        if (l == 0) { ss[w] = s; bc[w] = b + b_out[w]; }
    }
    __syncthreads();

    int m = (blockIdx.x << 3) + w;
    const float* xr = X + (size_t)m * DD;

    float f[16];
    #pragma unroll
    for (int i = 0; i < 16; i++) f[i] = xr[i * 32 + l];

    float mx = f[0];
    #pragma unroll
    for (int i = 1; i < 16; i++) mx = fmaxf(mx, f[i]);
    #pragma unroll
    for (int off = 16; off > 0; off >>= 1)
        mx = fmaxf(mx, __shfl_xor_sync(0xffffffffu, mx, off));

    float se = 0.0f;
    #pragma unroll
    for (int i = 0; i < 16; i++) se += __expf(f[i] - mx);
    #pragma unroll
    for (int off = 16; off > 0; off >>= 1)
        se += __shfl_xor_sync(0xffffffffu, se, off);
    float c = mx + __logf(se);

    #pragma unroll
    for (int n = 0; n < NCLS; n++) {
        float dot = 0.0f;
        const float* wr = Wc + n * DD;
        #pragma unroll
        for (int i = 0; i < 16; i++) dot += f[i] * wr[i * 32 + l];
        #pragma unroll
        for (int off = 16; off > 0; off >>= 1)
            dot += __shfl_xor_sync(0xffffffffu, dot, off);
        if (l == 0) out[m * NCLS + n] = dot - c * ss[n] + bc[n];
    }
}

// ---------------------------------------------------------------------------
// kernel_launch — 6 launches total
// ---------------------------------------------------------------------------
extern "C" void kernel_launch(void* const* d_in, const int* in_sizes, int n_in,
                              void* d_out, int out_size) {
    (void)in_sizes; (void)out_size;
    if (n_in < 17) return;
    const float* x0     = (const float*)d_in[0];
    const float* W_ih   = (const float*)d_in[3];
    const float* W_hh   = (const float*)d_in[4];
    const float* b_ih   = (const float*)d_in[5];
    const float* b_hh   = (const float*)d_in[6];
    const float* W1     = (const float*)d_in[7];
    const float* bb1    = (const float*)d_in[8];
    const float* W2     = (const float*)d_in[9];
    const float* bb2    = (const float*)d_in[10];
    const float* W3     = (const float*)d_in[11];
    const float* bb3    = (const float*)d_in[12];
    const float* W_half = (const float*)d_in[13];
    const float* b_half = (const float*)d_in[14];
    const float* W_out  = (const float*)d_in[15];
    const float* b_out  = (const float*)d_in[16];
    float* out = (float*)d_out;

    float *gx, *x3;
    __nv_bfloat16 *A0, *e2, *x1b, *x2b, *Wih2, *W12, *W22, *W32;
    cudaGetSymbolAddress((void**)&gx,   g_gx);
    cudaGetSymbolAddress((void**)&x3,   g_x3);
    cudaGetSymbolAddress((void**)&A0,   g_A0);
    cudaGetSymbolAddress((void**)&e2,   g_e2);
    cudaGetSymbolAddress((void**)&x1b,  g_x1b);
    cudaGetSymbolAddress((void**)&x2b,  g_x2b);
    cudaGetSymbolAddress((void**)&Wih2, g_Wih2);
    cudaGetSymbolAddress((void**)&W12,  g_W12);
    cudaGetSymbolAddress((void**)&W22,  g_W22);
    cudaGetSymbolAddress((void**)&W32,  g_W32);

    cudaFuncSetAttribute(k_scan, cudaFuncAttributeMaxDynamicSharedMemorySize,
                         SCAN_SMEM_BYTES);
    cudaFuncSetAttribute(k_mma_gemm, cudaFuncAttributeMaxDynamicSharedMemorySize,
                         GEMM_SMEM);

    // 0: ALL preprocessing (splits, h zero, counters, Wc fold)
    k_pre<<<PRE_BLOCKS, 256>>>(x0, W_ih, W1, W2, W3, W_half, W_out);
    // 1: gx = x0 @ W_ih^T + b_ih   [32768 x 1536]  (128x128 tiles, BK=64)
    k_mma_gemm<<<256 * 12, 256, GEMM_SMEM>>>(A0, Wih2, b_ih, gx, 1536, 12, 0);
    // 2: GRU scan (256 steps) -> e2 planes
    k_scan<<<128, 256, SCAN_SMEM_BYTES>>>(W_hh, b_hh);
    // 3-5: FFN (128x128 tiles, BK=64)
    k_mma_gemm<<<256 * 4, 256, GEMM_SMEM>>>(e2,  W12, bb1, x1b, 512, 4, 1);
    k_mma_gemm<<<256 * 4, 256, GEMM_SMEM>>>(x1b, W22, bb2, x2b, 512, 4, 1);
    k_mma_gemm<<<256 * 4, 256, GEMM_SMEM>>>(x2b, W32, bb3, x3,  512, 4, 0);
    // 6: fused log_softmax + combined classifier head (prep2 inlined)
    k_final<<<MROWS / 8, 256>>>(x3, W_out, b_half, b_out, out);
}

// round 17
// speedup vs baseline: 1.2913x; 1.0027x over previous
#include <cuda_runtime.h>
#include <cuda_bf16.h>
#include <cstddef>
#include <cstdint>

// Problem constants
#define BB     128
#define TT     512
#define HALF_T 256
#define DD     512
#define NCLS   7
#define MROWS  (BB * HALF_T)   // 32768 rows fed to FFN / head

typedef unsigned long long ull;

// ---------------------------------------------------------------------------
// mma.sync / ldmatrix / cp.async / bulk-DMA helpers (baseline PTX, sm_100-safe)
// ---------------------------------------------------------------------------
__device__ __forceinline__ uint32_t smem_u32(const void* p) {
    uint32_t a;
    asm("{ .reg .u64 t; cvta.to.shared.u64 t, %1; cvt.u32.u64 %0, t; }"
        : "=r"(a) : "l"(p));
    return a;
}
__device__ __forceinline__ void ldsm4(uint32_t* r, uint32_t addr) {
    asm volatile("ldmatrix.sync.aligned.m8n8.x4.shared.b16 {%0,%1,%2,%3}, [%4];"
        : "=r"(r[0]), "=r"(r[1]), "=r"(r[2]), "=r"(r[3]) : "r"(addr));
}
__device__ __forceinline__ void mma_bf16(float* d, const uint32_t* a,
                                         uint32_t b0, uint32_t b1) {
    asm volatile("mma.sync.aligned.m16n8k16.row.col.f32.bf16.bf16.f32 "
        "{%0,%1,%2,%3}, {%4,%5,%6,%7}, {%8,%9}, {%0,%1,%2,%3};"
        : "+f"(d[0]), "+f"(d[1]), "+f"(d[2]), "+f"(d[3])
        : "r"(a[0]), "r"(a[1]), "r"(a[2]), "r"(a[3]), "r"(b0), "r"(b1));
}
__device__ __forceinline__ void cpasync16(uint32_t dst, const void* src) {
    asm volatile("cp.async.cg.shared.global [%0], [%1], 16;"
                 :: "r"(dst), "l"(src));
}
#define CP_COMMIT() asm volatile("cp.async.commit_group;" ::: "memory")

// bulk DMA: gmem -> smem, completion via mbarrier complete_tx
__device__ __forceinline__ void bulkcp(uint32_t dst, const void* src,
                                       uint32_t bytes, uint32_t mbar) {
    asm volatile(
        "cp.async.bulk.shared::cluster.global.mbarrier::complete_tx::bytes "
        "[%0], [%1], %2, [%3];"
        :: "r"(dst), "l"(src), "r"(bytes), "r"(mbar) : "memory");
}
__device__ __forceinline__ void mbar_init(uint32_t mbar, uint32_t cnt) {
    asm volatile("mbarrier.init.shared.b64 [%0], %1;"
                 :: "r"(mbar), "r"(cnt) : "memory");
}
__device__ __forceinline__ void mbar_expect(uint32_t mbar, uint32_t bytes) {
    asm volatile("mbarrier.arrive.expect_tx.shared.b64 _, [%0], %1;"
                 :: "r"(mbar), "r"(bytes) : "memory");
}
__device__ __forceinline__ void mbar_wait(uint32_t mbar, uint32_t parity) {
    asm volatile("{\n\t.reg .pred P;\n\tWL%=:\n\t"
                 "mbarrier.try_wait.parity.acquire.cta.shared::cta.b64 P, [%0], %1;\n\t"
                 "@!P bra WL%=;\n\t}" :: "r"(mbar), "r"(parity) : "memory");
}
__device__ __forceinline__ void arrive_release(unsigned* ctr) {
    unsigned old;
    asm volatile("atom.release.gpu.global.add.u32 %0, [%1], 1;"
                 : "=r"(old) : "l"(ctr) : "memory");
}
__device__ __forceinline__ unsigned ld_acquire(const unsigned* ctr) {
    unsigned v;
    asm volatile("ld.acquire.gpu.global.u32 %0, [%1];"
                 : "=r"(v) : "l"(ctr) : "memory");
    return v;
}

// ---------------------------------------------------------------------------
// Device scratch
// ---------------------------------------------------------------------------
__device__ float g_gx[MROWS * 1536];             // input projections (fp32)
__device__ float g_x3[MROWS * DD];               // FFN layer-3 output (fp32)
__device__ __nv_bfloat16 g_A0 [MROWS * 1024];    // x0 split planes (hi|lo)
__device__ __nv_bfloat16 g_e2 [MROWS * 1024];    // emotions split planes
__device__ __nv_bfloat16 g_x1b[MROWS * 1024];
__device__ __nv_bfloat16 g_x2b[MROWS * 1024];
__device__ __nv_bfloat16 g_Wih2[1536 * 1024];    // weight split planes
__device__ __nv_bfloat16 g_W12 [512 * 1024];
__device__ __nv_bfloat16 g_W22 [512 * 1024];
__device__ __nv_bfloat16 g_W32 [512 * 1024];
// GRU h planes, padded layout for bulk DMA:
// [2 bufs][4 groups][2 planes][32 batches][520]  (row = plane*32+batch)
#define HROW 520
#define HGRP (2 * 32 * HROW)                     // 33280 elems / 66560 B
__device__ __nv_bfloat16 g_h2[2 * 4 * HGRP];
__device__ float g_Wc[NCLS * DD];
__device__ unsigned g_ctr4[4 * 32];              // barrier counters, 128B apart

// ---------------------------------------------------------------------------
// split helper: fp32 row chunk -> bf16 hi/lo planes
// ---------------------------------------------------------------------------
__device__ __forceinline__ void split_row(const float* src, __nv_bfloat16* dst,
                                          size_t so, size_t dro, int c4) {
    float4 v = *(const float4*)(src + so + c4);
    __nv_bfloat16 h[4], lo[4];
    float vv[4] = {v.x, v.y, v.z, v.w};
    #pragma unroll
    for (int i = 0; i < 4; i++) {
        h[i] = __float2bfloat16(vv[i]);
        lo[i] = __float2bfloat16(vv[i] - __bfloat162float(h[i]));
    }
    *(ull*)(dst + dro + c4)       = *(ull*)h;
    *(ull*)(dst + dro + 512 + c4) = *(ull*)lo;
}

// ---------------------------------------------------------------------------
// k_pre: ALL preprocessing in one launch (R16 proven).
// ---------------------------------------------------------------------------
#define PRE_X0   (MROWS * 128)                   // 4194304
#define PRE_WIH  (PRE_X0 + 1536 * 128)           // 4390912
#define PRE_W123 (PRE_WIH + 3 * 512 * 128)       // 4587520
#define PRE_HZ   (PRE_W123 + 4 * HGRP / 2)       // 4654080
#define PRE_WC   (PRE_HZ + NCLS * DD)            // 4657664
#define PRE_END  (PRE_WC + 4)                    // 4657668
#define PRE_BLOCKS ((PRE_END + 255) / 256)

__global__ void k_pre(const float* __restrict__ x0,
                      const float* __restrict__ W_ih,
                      const float* __restrict__ W1,
                      const float* __restrict__ W2,
                      const float* __restrict__ W3,
                      const float* __restrict__ W_half,
                      const float* __restrict__ W_out) {
    int idx = blockIdx.x * 256 + threadIdx.x;
    if (idx < PRE_X0) {
        int r = idx >> 7, c4 = (idx & 127) << 2;
        size_t so = (size_t)((r >> 8) * 512 + (r & 255)) * 512;
        split_row(x0, g_A0, so, (size_t)r * 1024, c4);
    } else if (idx < PRE_WIH) {
        int u = idx - PRE_X0;
        int r = u >> 7, c4 = (u & 127) << 2;
        split_row(W_ih, g_Wih2, (size_t)r * 512, (size_t)r * 1024, c4);
    } else if (idx < PRE_W123) {
        int u = idx - PRE_WIH;
        int which = u / (512 * 128);
        int rem = u - which * (512 * 128);
        int r = rem >> 7, c4 = (rem & 127) << 2;
        const float* src = (which == 0) ? W1 : (which == 1) ? W2 : W3;
        __nv_bfloat16* dst = (which == 0) ? g_W12 : (which == 1) ? g_W22 : g_W32;
        split_row(src, dst, (size_t)r * 512, (size_t)r * 1024, c4);
    } else if (idx < PRE_HZ) {
        int u = idx - PRE_W123;
        ((__nv_bfloat162*)g_h2)[u] = __nv_bfloat162{__nv_bfloat16(0.f),
                                                    __nv_bfloat16(0.f)};
    } else if (idx < PRE_WC) {
        int u = idx - PRE_HZ;
        int n = u / DD, k = u - n * DD;
        float s = 0.0f;
        for (int j = 0; j < 256; j++)
            s += W_out[n * 256 + j] * W_half[j * DD + k];
        g_Wc[u] = s;
    } else if (idx < PRE_END) {
        g_ctr4[(idx - PRE_WC) * 32] = 0u;
    }
}

// ---------------------------------------------------------------------------
// mma.sync bf16-split GEMM, 128x128 tile, BK=64 (24 chunks), 3-stage pipeline
// (exact R14/R15 config).
// ---------------------------------------------------------------------------
#define ROWB 144         // padded smem row: 64 bf16 (128B) + 16B pad
#define BUFB (128 * ROWB)    // 18432
#define NST  3
#define GEMM_SMEM (2 * NST * BUFB)   // 110592

__global__ void __launch_bounds__(256, 2)
k_mma_gemm(const __nv_bfloat16* __restrict__ A,
           const __nv_bfloat16* __restrict__ Bw,
           const float* __restrict__ bias,
           void* __restrict__ Cout,
           int Ntot, int n_tiles, int mode) {
    extern __shared__ __align__(16) char smc[];
    uint32_t sbase = smem_u32(smc);
    int tid = threadIdx.x, wid = tid >> 5, lane = tid & 31;
    int m0 = (blockIdx.x / n_tiles) << 7;
    int n0 = (blockIdx.x % n_tiles) << 7;

    int sr2 = tid >> 3;
    int sc2 = tid & 7;

    float acc[2][8][4];
    #pragma unroll
    for (int i = 0; i < 2; i++)
        #pragma unroll
        for (int j = 0; j < 8; j++)
            #pragma unroll
            for (int q = 0; q < 4; q++) acc[i][j][q] = 0.0f;

    auto issue = [&](int c) {
        int seg = c >> 3, kofs = (c & 7) << 6;
        int asel = (seg == 1) ? 512 : 0;
        int bsel = (seg == 2) ? 512 : 0;
        const __nv_bfloat16* Ag = A + (size_t)m0 * 1024 + asel + kofs;
        const __nv_bfloat16* Bg = Bw + (size_t)n0 * 1024 + bsel + kofs;
        int buf = c % NST;
        uint32_t da = sbase + (uint32_t)buf * BUFB;
        uint32_t db = sbase + (uint32_t)(NST + buf) * BUFB;
        #pragma unroll
        for (int rr = 0; rr < 4; rr++) {
            int row = sr2 + rr * 32;
            cpasync16(da + row * ROWB + sc2 * 16, Ag + (size_t)row * 1024 + sc2 * 8);
            cpasync16(db + row * ROWB + sc2 * 16, Bg + (size_t)row * 1024 + sc2 * 8);
        }
        CP_COMMIT();
    };

    issue(0);
    issue(1);

    int wm = wid & 3;
    int wn = wid >> 2;
    uint32_t a_row  = (uint32_t)(wm * 32 + (lane & 15));
    uint32_t a_colb = (uint32_t)((lane >> 4) * 16);
    uint32_t b_row  = (uint32_t)(wn * 64 + (lane & 7));
    uint32_t b_colb = (uint32_t)((lane >> 3) * 16);

    for (int c = 0; c < 24; c++) {
        if (c < 23) asm volatile("cp.async.wait_group 1;" ::: "memory");
        else        asm volatile("cp.async.wait_group 0;" ::: "memory");
        __syncthreads();
        if (c + 2 < 24) issue(c + 2);

        int buf = c % NST;
        uint32_t sA = sbase + (uint32_t)buf * BUFB;
        uint32_t sB = sbase + (uint32_t)(NST + buf) * BUFB;

        #pragma unroll
        for (int kh = 0; kh < 2; kh++) {
            uint32_t bf[8][4];
            #pragma unroll
            for (int nt = 0; nt < 8; nt++)
                ldsm4(bf[nt], sB + (b_row + nt * 8) * ROWB + kh * 64 + b_colb);

            #pragma unroll
            for (int ks = 0; ks < 2; ks++) {
                uint32_t af[2][4];
                ldsm4(af[0], sA + a_row * ROWB + kh * 64 + ks * 32 + a_colb);
                ldsm4(af[1], sA + (a_row + 16) * ROWB + kh * 64 + ks * 32 + a_colb);
                #pragma unroll
                for (int mi = 0; mi < 2; mi++)
                    #pragma unroll
                    for (int nt = 0; nt < 8; nt++)
                        mma_bf16(acc[mi][nt], af[mi], bf[nt][2 * ks], bf[nt][2 * ks + 1]);
            }
        }
    }

    int gid = lane >> 2, tig = lane & 3;
    float bv[16];
    #pragma unroll
    for (int nt = 0; nt < 8; nt++) {
        int col = n0 + wn * 64 + nt * 8 + 2 * tig;
        bv[nt * 2]     = bias[col];
        bv[nt * 2 + 1] = bias[col + 1];
    }
    #pragma unroll
    for (int mi = 0; mi < 2; mi++) {
        int mrow = m0 + wm * 32 + mi * 16 + gid;
        #pragma unroll
        for (int nt = 0; nt < 8; nt++) {
            int col = n0 + wn * 64 + nt * 8 + 2 * tig;
            float v0 = acc[mi][nt][0] + bv[nt * 2];
            float v1 = acc[mi][nt][1] + bv[nt * 2 + 1];
            float v2 = acc[mi][nt][2] + bv[nt * 2];
            float v3 = acc[mi][nt][3] + bv[nt * 2 + 1];
            if (mode == 0) {
                float* C = (float*)Cout;
                float2 p0 = {v0, v1}, p1 = {v2, v3};
                *(float2*)&C[(size_t)mrow * Ntot + col]       = p0;
                *(float2*)&C[(size_t)(mrow + 8) * Ntot + col] = p1;
            } else {
                __nv_bfloat16* C = (__nv_bfloat16*)Cout;
                v0 = tanhf(v0); v1 = tanhf(v1); v2 = tanhf(v2); v3 = tanhf(v3);
                __nv_bfloat16 h0 = __float2bfloat16(v0), h1 = __float2bfloat16(v1);
                __nv_bfloat16 h2 = __float2bfloat16(v2), h3 = __float2bfloat16(v3);
                __nv_bfloat16 l0 = __float2bfloat16(v0 - __bfloat162float(h0));
                __nv_bfloat16 l1 = __float2bfloat16(v1 - __bfloat162float(h1));
                __nv_bfloat16 l2 = __float2bfloat16(v2 - __bfloat162float(h2));
                __nv_bfloat16 l3 = __float2bfloat16(v3 - __bfloat162float(h3));
                __nv_bfloat162 ph0 = {h0, h1}, ph1 = {h2, h3};
                __nv_bfloat162 pl0 = {l0, l1}, pl1 = {l2, l3};
                *(__nv_bfloat162*)&C[(size_t)mrow * 1024 + col]             = ph0;
                *(__nv_bfloat162*)&C[(size_t)mrow * 1024 + 512 + col]       = pl0;
                *(__nv_bfloat162*)&C[(size_t)(mrow + 8) * 1024 + col]       = ph1;
                *(__nv_bfloat162*)&C[(size_t)(mrow + 8) * 1024 + 512 + col] = pl1;
            }
        }
    }
}

// ---------------------------------------------------------------------------
// Persistent GRU scan: 384 threads, 12 mma warps, k-split over 2 warp sets,
// BOTH W planes in registers (zero W ldsm per step), 2 partial gh buffers.
// ---------------------------------------------------------------------------
#define SC_STRIDE 520                            // bf16 elems/row -> 1040 B
#define SC_W_BYTES (96 * SC_STRIDE * 2)          // 99840
#define SC_H_BYTES (64 * SC_STRIDE * 2)          // 66560
#define SC_GH_F    (48 * 33)
#define SCAN_SMEM_BYTES (SC_W_BYTES + SC_H_BYTES + 2 * SC_GH_F * 4 + 256)

__global__ void __launch_bounds__(384, 1)
k_scan(const float* __restrict__ Whh, const float* __restrict__ bhh) {
    extern __shared__ __align__(16) char dynsm[];
    __nv_bfloat16* ws  = (__nv_bfloat16*)dynsm;
    __nv_bfloat16* hsb = (__nv_bfloat16*)(dynsm + SC_W_BYTES);
    float* gh  = (float*)(dynsm + SC_W_BYTES + SC_H_BYTES);   // 2 partials
    float* bsh = gh + 2 * SC_GH_F;
    uint32_t ws_u = smem_u32(ws);
    uint32_t hs_u = smem_u32(hsb);
    uint32_t mbA1 = smem_u32(dynsm + SC_W_BYTES + SC_H_BYTES
                             + 2 * SC_GH_F * 4 + 192);
    uint32_t mbA2 = mbA1 + 8;
    uint32_t mbB  = mbA1 + 16;

    int tid = threadIdx.x, wid = tid >> 5, lane = tid & 31;
    int blk = blockIdx.x;
    int bg = blk >> 5, dg = blk & 31;
    int d0 = dg << 4, b0 = bg << 5;

    // Load W slice once, split into bf16 hi/lo plane rows.
    for (int i = tid; i < 48 * 512; i += 384) {
        int j = i >> 9, k = i & 511;            // j = gate*16 + dc
        int g = j >> 4, dc = j & 15;
        float w = Whh[(size_t)(g * 512 + d0 + dc) * 512 + k];
        __nv_bfloat16 hi = __float2bfloat16(w);
        __nv_bfloat16 lo = __float2bfloat16(w - __bfloat162float(hi));
        ws[j * SC_STRIDE + k]        = hi;
        ws[(48 + j) * SC_STRIDE + k] = lo;
    }
    if (tid < 48) bsh[tid] = bhh[(tid >> 4) * 512 + d0 + (tid & 15)];
    if (tid == 0) { mbar_init(mbA1, 1); mbar_init(mbA2, 1); mbar_init(mbB, 1); }
    __syncthreads();

    int kh2 = wid / 6;                           // k half (0/1)
    int sub = wid - kh2 * 6;
    int mt = sub % 3, nh = sub / 3;
    int kbase = kh2 << 3;                        // k32 base (0 or 8)
    uint32_t aw_hi = ws_u + (uint32_t)((mt * 16 + (lane & 15)) * 1040)
                   + ((lane >> 4) << 4);
    uint32_t aw_lo = aw_hi + 48u * 1040u;
    uint32_t bh_hi = hs_u + (uint32_t)((nh * 16 + (lane & 7)) * 1040)
                   + ((lane >> 3) << 4);
    uint32_t bh_lo = bh_hi + 32u * 1040u;
    uint32_t mbHi = (nh == 0) ? mbA1 : mbA2;
    float* ghp = gh + kh2 * SC_GH_F;

    // Hoist BOTH W planes for this warp's k-range into registers.
    uint32_t ahr[8][2][4], alr[8][2][4];
    #pragma unroll
    for (int k = 0; k < 8; k++) {
        int kb = (kbase + k) << 6;
        ldsm4(ahr[k][0], aw_hi + kb);
        ldsm4(ahr[k][1], aw_hi + kb + 32);
        ldsm4(alr[k][0], aw_lo + kb);
        ldsm4(alr[k][1], aw_lo + kb + 32);
    }

    int bi_a = tid >> 4;                        // 0..23 (first output)
    int dc_a = tid & 15;
    int d_a = d0 + dc_a;
    int bi_b = 24 + (tid >> 4);                 // second output (tid<128)
    int p = 0;

    for (int t = 0; t < HALF_T; t++) {
        // prefetch gx gate values (overlaps DMA)
        float gxv0[3], gxv1[3];
        {
            size_t row = ((size_t)(b0 + bi_a) * 256 + t) * 1536;
            gxv0[0] = __ldcg(g_gx + row + d_a);
            gxv0[1] = __ldcg(g_gx + row + 512 + d_a);
            gxv0[2] = __ldcg(g_gx + row + 1024 + d_a);
            if (tid < 128) {
                size_t row2 = ((size_t)(b0 + bi_b) * 256 + t) * 1536;
                gxv1[0] = __ldcg(g_gx + row2 + d_a);
                gxv1[1] = __ldcg(g_gx + row2 + 512 + d_a);
                gxv1[2] = __ldcg(g_gx + row2 + 1024 + d_a);
            }
        }

        // bulk-DMA stage h planes: hi half 1, hi half 2, lo block
        if (tid == 0) {
            const __nv_bfloat16* src = g_h2 + ((size_t)p * 4 + bg) * HGRP;
            mbar_expect(mbA1, 16640u);
            mbar_expect(mbA2, 16640u);
            mbar_expect(mbB,  33280u);
            bulkcp(hs_u,          src,         16640u, mbA1);
            bulkcp(hs_u + 16640u, src + 8320,  16640u, mbA2);
            bulkcp(hs_u + 33280u, src + 16640, 33280u, mbB);
        }

        // hi phase: (Whi + Wlo) x h_hi — warp waits only its hi half
        mbar_wait(mbHi, (uint32_t)(t & 1));
        float acc[2][4];
        #pragma unroll
        for (int nt = 0; nt < 2; nt++)
            #pragma unroll
            for (int q = 0; q < 4; q++) acc[nt][q] = 0.0f;
        #pragma unroll
        for (int k = 0; k < 8; k++) {
            int kb = (kbase + k) << 6;
            uint32_t bf0[4], bf1[4];
            ldsm4(bf0, bh_hi + kb);
            ldsm4(bf1, bh_hi + kb + 8 * 1040);
            mma_bf16(acc[0], ahr[k][0], bf0[0], bf0[1]);
            mma_bf16(acc[1], ahr[k][0], bf1[0], bf1[1]);
            mma_bf16(acc[0], ahr[k][1], bf0[2], bf0[3]);
            mma_bf16(acc[1], ahr[k][1], bf1[2], bf1[3]);
            mma_bf16(acc[0], alr[k][0], bf0[0], bf0[1]);
            mma_bf16(acc[1], alr[k][0], bf1[0], bf1[1]);
            mma_bf16(acc[0], alr[k][1], bf0[2], bf0[3]);
            mma_bf16(acc[1], alr[k][1], bf1[2], bf1[3]);
        }
        mbar_wait(mbB, (uint32_t)(t & 1));      // lo plane visible
        #pragma unroll
        for (int k = 0; k < 8; k++) {
            int kb = (kbase + k) << 6;
            uint32_t bl0[4], bl1[4];
            ldsm4(bl0, bh_lo + kb);
            ldsm4(bl1, bh_lo + kb + 8 * 1040);
            mma_bf16(acc[0], ahr[k][0], bl0[0], bl0[1]);
            mma_bf16(acc[1], ahr[k][0], bl1[0], bl1[1]);
            mma_bf16(acc[0], ahr[k][1], bl0[2], bl0[3]);
            mma_bf16(acc[1], ahr[k][1], bl1[2], bl1[3]);
        }
        // write gh fragments (partial buffer kh2)
        {
            int r = lane >> 2, c = (lane & 3) << 1;
            #pragma unroll
            for (int nt = 0; nt < 2; nt++) {
                int n = nh * 16 + nt * 8 + c;
                int m = mt * 16 + r;
                ghp[m * 33 + n]           = acc[nt][0];
                ghp[m * 33 + n + 1]       = acc[nt][1];
                ghp[(m + 8) * 33 + n]     = acc[nt][2];
                ghp[(m + 8) * 33 + n + 1] = acc[nt][3];
            }
        }
        __syncthreads();

        // epilogue: q=0 all threads (bi_a), q=1 tid<128 (bi_b)
        __nv_bfloat16 ehi[2], elo[2];
        #pragma unroll
        for (int q = 0; q < 2; q++) {
            if (q == 0 || tid < 128) {
                int bi = q ? bi_b : bi_a;
                const float* gv = q ? gxv1 : gxv0;
                float ghr = gh[dc_a * 33 + bi] + gh[SC_GH_F + dc_a * 33 + bi]
                          + bsh[dc_a];
                float ghz = gh[(16 + dc_a) * 33 + bi]
                          + gh[SC_GH_F + (16 + dc_a) * 33 + bi] + bsh[16 + dc_a];
                float ghn = gh[(32 + dc_a) * 33 + bi]
                          + gh[SC_GH_F + (32 + dc_a) * 33 + bi] + bsh[32 + dc_a];
                float r = 1.0f / (1.0f + __expf(-(gv[0] + ghr)));
                float z = 1.0f / (1.0f + __expf(-(gv[1] + ghz)));
                float n = tanhf(gv[2] + r * ghn);
                float hold = __bfloat162float(hsb[bi * SC_STRIDE + d_a])
                           + __bfloat162float(hsb[(32 + bi) * SC_STRIDE + d_a]);
                float hn = (1.0f - z) * n + z * hold;
                __nv_bfloat16 hi = __float2bfloat16(hn);
                __nv_bfloat16 lo = __float2bfloat16(hn - __bfloat162float(hi));
                ehi[q] = hi; elo[q] = lo;
                if (t < HALF_T - 1) {
                    size_t gb = ((size_t)(p ^ 1) * 4 + bg) * HGRP;
                    g_h2[gb + bi * HROW + d_a]         = hi;
                    g_h2[gb + 16640 + bi * HROW + d_a] = lo;
                }
            }
        }

        if (t < HALF_T - 1) {
            __syncthreads();                     // all h stores issued
            if (tid == 0) arrive_release(&g_ctr4[bg * 32]);
        }

        // e2 stores overlap the peer wait
        #pragma unroll
        for (int q = 0; q < 2; q++) {
            if (q == 0 || tid < 128) {
                int bi = q ? bi_b : bi_a;
                size_t erow = ((size_t)(b0 + bi) * 256 + t) * 1024;
                g_e2[erow + d_a]       = ehi[q];
                g_e2[erow + 512 + d_a] = elo[q];
            }
        }

        if (t < HALF_T - 1) {
            if (tid == 0) {
                unsigned target = (unsigned)(t + 1) * 32u;
                while (ld_acquire(&g_ctr4[bg * 32]) < target) { }
            }
            __syncthreads();
        }
        p ^= 1;
    }
}

// ---------------------------------------------------------------------------
// Fused head: out[m] = logsoftmax(f[m]) @ W_comb^T + b_comb (prep2 inlined)
// ---------------------------------------------------------------------------
__global__ void __launch_bounds__(256)
k_final(const float* __restrict__ X,
        const float* __restrict__ W_out,
        const float* __restrict__ b_half,
        const float* __restrict__ b_out,
        float* __restrict__ out) {
    __shared__ float Wc[NCLS * DD];
    __shared__ float ss[NCLS], bc[NCLS];
    int tid = threadIdx.x;
    for (int idx = tid; idx < NCLS * DD; idx += 256) Wc[idx] = g_Wc[idx];
    __syncthreads();

    int w = tid >> 5, l = tid & 31;
    if (w < NCLS) {
        float s = 0.0f;
        #pragma unroll
        for (int i = 0; i < 16; i++) s += Wc[w * DD + i * 32 + l];
        float b = 0.0f;
        #pragma unroll
        for (int i = 0; i < 8; i++)
            b += W_out[w * 256 + i * 32 + l] * b_half[i * 32 + l];
        #pragma unroll
        for (int off = 16; off > 0; off >>= 1) {
            s += __shfl_xor_sync(0xffffffffu, s, off);
            b += __shfl_xor_sync(0xffffffffu, b, off);
        }
        if (l == 0) { ss[w] = s; bc[w] = b + b_out[w]; }
    }
    __syncthreads();

    int m = (blockIdx.x << 3) + w;
    const float* xr = X + (size_t)m * DD;

    float f[16];
    #pragma unroll
    for (int i = 0; i < 16; i++) f[i] = xr[i * 32 + l];

    float mx = f[0];
    #pragma unroll
    for (int i = 1; i < 16; i++) mx = fmaxf(mx, f[i]);
    #pragma unroll
    for (int off = 16; off > 0; off >>= 1)
        mx = fmaxf(mx, __shfl_xor_sync(0xffffffffu, mx, off));

    float se = 0.0f;
    #pragma unroll
    for (int i = 0; i < 16; i++) se += __expf(f[i] - mx);
    #pragma unroll
    for (int off = 16; off > 0; off >>= 1)
        se += __shfl_xor_sync(0xffffffffu, se, off);
    float c = mx + __logf(se);

    #pragma unroll
    for (int n = 0; n < NCLS; n++) {
        float dot = 0.0f;
        const float* wr = Wc + n * DD;
        #pragma unroll
        for (int i = 0; i < 16; i++) dot += f[i] * wr[i * 32 + l];
        #pragma unroll
        for (int off = 16; off > 0; off >>= 1)
            dot += __shfl_xor_sync(0xffffffffu, dot, off);
        if (l == 0) out[m * NCLS + n] = dot - c * ss[n] + bc[n];
    }
}

// ---------------------------------------------------------------------------
// kernel_launch — 7 launches
// ---------------------------------------------------------------------------
extern "C" void kernel_launch(void* const* d_in, const int* in_sizes, int n_in,
                              void* d_out, int out_size) {
    (void)in_sizes; (void)out_size;
    if (n_in < 17) return;
    const float* x0     = (const float*)d_in[0];
    const float* W_ih   = (const float*)d_in[3];
    const float* W_hh   = (const float*)d_in[4];
    const float* b_ih   = (const float*)d_in[5];
    const float* b_hh   = (const float*)d_in[6];
    const float* W1     = (const float*)d_in[7];
    const float* bb1    = (const float*)d_in[8];
    const float* W2     = (const float*)d_in[9];
    const float* bb2    = (const float*)d_in[10];
    const float* W3     = (const float*)d_in[11];
    const float* bb3    = (const float*)d_in[12];
    const float* W_half = (const float*)d_in[13];
    const float* b_half = (const float*)d_in[14];
    const float* W_out  = (const float*)d_in[15];
    const float* b_out  = (const float*)d_in[16];
    float* out = (float*)d_out;

    float *gx, *x3;
    __nv_bfloat16 *A0, *e2, *x1b, *x2b, *Wih2, *W12, *W22, *W32;
    cudaGetSymbolAddress((void**)&gx,   g_gx);
    cudaGetSymbolAddress((void**)&x3,   g_x3);
    cudaGetSymbolAddress((void**)&A0,   g_A0);
    cudaGetSymbolAddress((void**)&e2,   g_e2);
    cudaGetSymbolAddress((void**)&x1b,  g_x1b);
    cudaGetSymbolAddress((void**)&x2b,  g_x2b);
    cudaGetSymbolAddress((void**)&Wih2, g_Wih2);
    cudaGetSymbolAddress((void**)&W12,  g_W12);
    cudaGetSymbolAddress((void**)&W22,  g_W22);
    cudaGetSymbolAddress((void**)&W32,  g_W32);

    cudaFuncSetAttribute(k_scan, cudaFuncAttributeMaxDynamicSharedMemorySize,
                         SCAN_SMEM_BYTES);
    cudaFuncSetAttribute(k_mma_gemm, cudaFuncAttributeMaxDynamicSharedMemorySize,
                         GEMM_SMEM);

    // 0: ALL preprocessing (splits, h zero, counters, Wc fold)
    k_pre<<<PRE_BLOCKS, 256>>>(x0, W_ih, W1, W2, W3, W_half, W_out);
    // 1: gx = x0 @ W_ih^T + b_ih   [32768 x 1536]  (128x128 tiles, BK=64)
    k_mma_gemm<<<256 * 12, 256, GEMM_SMEM>>>(A0, Wih2, b_ih, gx, 1536, 12, 0);
    // 2: GRU scan (256 steps) -> e2 planes  (384 threads, 12 mma warps)
    k_scan<<<128, 384, SCAN_SMEM_BYTES>>>(W_hh, b_hh);
    // 3-5: FFN (128x128 tiles, BK=64)
    k_mma_gemm<<<256 * 4, 256, GEMM_SMEM>>>(e2,  W12, bb1, x1b, 512, 4, 1);
    k_mma_gemm<<<256 * 4, 256, GEMM_SMEM>>>(x1b, W22, bb2, x2b, 512, 4, 1);
    k_mma_gemm<<<256 * 4, 256, GEMM_SMEM>>>(x2b, W32, bb3, x3,  512, 4, 0);
    // 6: fused log_softmax + combined classifier head (prep2 inlined)
    k_final<<<MROWS / 8, 256>>>(x3, W_out, b_half, b_out, out);
}